// round 2
// baseline (speedup 1.0000x reference)
#include <cuda_runtime.h>
#include <math.h>

// ---------------- problem constants ----------------
#define BB    4
#define CCH   256
#define C2H   128
#define HO    63
#define WO    63
#define NPIX  (HO*WO)      // 3969
#define HIN   128
#define WIN   128
#define EPSV  1e-5f
#define PAD   16384        // OOB-read padding for tail chunks

// ---------------- scratch (device globals) ----------------
__device__ float g_xp    [BB*CCH*NPIX];                // pooled (B,C,N) — also residual
__device__ float g_thetaT[BB*NPIX*C2H + PAD];          // (B,N,C2)
__device__ float g_phi   [BB*C2H*NPIX + PAD];          // (B,C2,N)
__device__ float g_gT    [BB*NPIX*C2H + PAD];          // (B,N,C2)
__device__ float g_S     [(size_t)BB*NPIX*NPIX + PAD]; // (B,N,N)
__device__ float g_y     [BB*NPIX*C2H + PAD];          // (B,N,C2) contiguous
__device__ float g_o2    [BB*CCH*NPIX];                // pre-BN (B,C,N)
__device__ float g_mean  [CCH];
__device__ float g_rstd  [CCH];

// ---------------- 3x3/2 VALID max pool ----------------
__global__ void pool_k(const float* __restrict__ x) {
    int idx = blockIdx.x * blockDim.x + threadIdx.x;
    if (idx >= BB*CCH*NPIX) return;
    int ow = idx % WO;
    int t  = idx / WO;
    int oh = t % HO;
    int bc = t / HO;
    const float* p = x + (size_t)bc * (HIN*WIN) + (oh*2) * WIN + (ow*2);
    float m = -INFINITY;
    #pragma unroll
    for (int i = 0; i < 3; i++) {
        m = fmaxf(m, p[i*WIN + 0]);
        m = fmaxf(m, p[i*WIN + 1]);
        m = fmaxf(m, p[i*WIN + 2]);
    }
    g_xp[idx] = m;
}

// ---------------- projection: out[o,n] = sum_k W[o,k]*xp[k,n] ----------------
// grid (16 n-chunks, 8 o-tiles, BB), 256 threads. Writes (C2,N) and/or (N,C2).
__global__ void proj_k(const float* __restrict__ W,   // (128,256) row-major
                       float* outCN,                   // (B,C2,N) or nullptr
                       float* outNC)                   // (B,N,C2) or nullptr
{
    __shared__ float sW[16][256];
    int t  = threadIdx.x;
    int b  = blockIdx.z;
    int o0 = blockIdx.y * 16;
    for (int i = t; i < 16*256; i += 256)
        sW[i >> 8][i & 255] = W[(o0 + (i >> 8)) * 256 + (i & 255)];
    __syncthreads();

    int n = blockIdx.x * 256 + t;
    bool ok = n < NPIX;
    const float* xb = g_xp + (size_t)b * CCH * NPIX;

    float acc[16];
    #pragma unroll
    for (int u = 0; u < 16; u++) acc[u] = 0.f;

    for (int k = 0; k < 256; k++) {
        float xv = ok ? xb[k * NPIX + n] : 0.f;
        #pragma unroll
        for (int u = 0; u < 16; u++)
            acc[u] = fmaf(sW[u][k], xv, acc[u]);
    }
    if (!ok) return;
    #pragma unroll
    for (int u = 0; u < 16; u++) {
        int o = o0 + u;
        if (outCN) outCN[(size_t)b * C2H * NPIX + (size_t)o * NPIX + n] = acc[u];
        if (outNC) outNC[(size_t)b * NPIX * C2H + (size_t)n * C2H + o] = acc[u];
    }
}

// ---------------- scores: S[n,m] = sum_c thetaT[n,c]*phi[c,m] ----------------
// grid (16 m-chunks, 497 n-tiles of 8, BB), 256 threads
__global__ void score_k() {
    __shared__ float sTh[8][128];
    int t  = threadIdx.x;
    int b  = blockIdx.z;
    int n0 = blockIdx.y * 8;
    const float* thb = g_thetaT + (size_t)b * NPIX * C2H;
    for (int i = t; i < 8*128; i += 256) {
        int r = i >> 7, c = i & 127;
        int n = n0 + r;
        sTh[r][c] = (n < NPIX) ? thb[(size_t)n * C2H + c] : 0.f;
    }
    __syncthreads();

    int m = blockIdx.x * 256 + t;
    bool ok = m < NPIX;
    const float* pb = g_phi + (size_t)b * C2H * NPIX;

    float acc[8];
    #pragma unroll
    for (int r = 0; r < 8; r++) acc[r] = 0.f;

    for (int c = 0; c < 128; c++) {
        float pv = ok ? pb[c * NPIX + m] : 0.f;
        #pragma unroll
        for (int r = 0; r < 8; r++)
            acc[r] = fmaf(sTh[r][c], pv, acc[r]);
    }
    if (!ok) return;
    float* Sb = g_S + (size_t)b * NPIX * NPIX;
    #pragma unroll
    for (int r = 0; r < 8; r++) {
        int n = n0 + r;
        if (n < NPIX) Sb[(size_t)n * NPIX + m] = acc[r];
    }
}

// ---------------- row softmax (in place on g_S) ----------------
__global__ void softmax_k() {
    size_t rowg = blockIdx.x;                 // B*N rows
    float* Srow = g_S + rowg * NPIX;
    int t = threadIdx.x;                      // 256
    __shared__ float red[256];

    float mx = -INFINITY;
    for (int m = t; m < NPIX; m += 256) mx = fmaxf(mx, Srow[m]);
    red[t] = mx; __syncthreads();
    for (int s = 128; s > 0; s >>= 1) {
        if (t < s) red[t] = fmaxf(red[t], red[t + s]);
        __syncthreads();
    }
    mx = red[0]; __syncthreads();

    float sum = 0.f;
    for (int m = t; m < NPIX; m += 256) {
        float e = expf(Srow[m] - mx);
        Srow[m] = e;
        sum += e;
    }
    red[t] = sum; __syncthreads();
    for (int s = 128; s > 0; s >>= 1) {
        if (t < s) red[t] += red[t + s];
        __syncthreads();
    }
    float inv = 1.f / red[0];
    for (int m = t; m < NPIX; m += 256) Srow[m] *= inv;
}

// ---------------- AV: y[n,c] = sum_m f[n,m]*gT[m,c] ----------------
// grid (993 n-tiles of 4, BB), 128 threads (= c)
__global__ void av_k() {
    __shared__ float sS[4][128];
    int t  = threadIdx.x;     // c
    int b  = blockIdx.y;
    int n0 = blockIdx.x * 4;
    const float* Sb  = g_S  + (size_t)b * NPIX * NPIX;
    const float* gTb = g_gT + (size_t)b * NPIX * C2H;

    float acc[4] = {0.f, 0.f, 0.f, 0.f};

    for (int m0 = 0; m0 < NPIX; m0 += 128) {
        for (int i = t; i < 4*128; i += 128) {
            int r = i >> 7, mm = i & 127;
            int n = n0 + r, m = m0 + mm;
            sS[r][mm] = (n < NPIX && m < NPIX) ? Sb[(size_t)n * NPIX + m] : 0.f;
        }
        __syncthreads();
        #pragma unroll 4
        for (int mm = 0; mm < 128; mm++) {
            // sS is zero for OOB m; gT has PAD tail so the read is safe
            float gv = gTb[(size_t)(m0 + mm) * C2H + t];
            #pragma unroll
            for (int r = 0; r < 4; r++)
                acc[r] = fmaf(sS[r][mm], gv, acc[r]);
        }
        __syncthreads();
    }
    #pragma unroll
    for (int r = 0; r < 4; r++) {
        int n = n0 + r;
        if (n < NPIX) g_y[(size_t)b * NPIX * C2H + (size_t)n * C2H + t] = acc[r];
    }
}

// ------------- out proj: o2[o,m] = sum_c y_w[o,c]*yview[c,m] -------------
// yview[c,m] = g_y flat [c*NPIX + m]  (the faithful raw view)
// grid (16 m-chunks, 16 o-tiles, BB), 256 threads
__global__ void outproj_k(const float* __restrict__ y_w) {  // (256,128)
    __shared__ float sW[16][128];
    int t  = threadIdx.x;
    int b  = blockIdx.z;
    int o0 = blockIdx.y * 16;
    for (int i = t; i < 16*128; i += 256)
        sW[i >> 7][i & 127] = y_w[(o0 + (i >> 7)) * 128 + (i & 127)];
    __syncthreads();

    int m = blockIdx.x * 256 + t;
    bool ok = m < NPIX;
    const float* yb = g_y + (size_t)b * NPIX * C2H;   // flat, read as (C2,N)

    float acc[16];
    #pragma unroll
    for (int u = 0; u < 16; u++) acc[u] = 0.f;

    for (int c = 0; c < 128; c++) {
        float yv = ok ? yb[(size_t)c * NPIX + m] : 0.f;
        #pragma unroll
        for (int u = 0; u < 16; u++)
            acc[u] = fmaf(sW[u][c], yv, acc[u]);
    }
    if (!ok) return;
    #pragma unroll
    for (int u = 0; u < 16; u++)
        g_o2[(size_t)b * CCH * NPIX + (size_t)(o0 + u) * NPIX + m] = acc[u];
}

// ---------------- BN stats (per channel over B,N) ----------------
__global__ void bnstats_k() {
    int c = blockIdx.x;
    int t = threadIdx.x;  // 256
    __shared__ double s1[256];
    __shared__ double s2[256];
    double a = 0.0, b2 = 0.0;
    for (int b = 0; b < BB; b++) {
        const float* p = g_o2 + (size_t)b * CCH * NPIX + (size_t)c * NPIX;
        for (int m = t; m < NPIX; m += 256) {
            double v = (double)p[m];
            a  += v;
            b2 += v * v;
        }
    }
    s1[t] = a; s2[t] = b2; __syncthreads();
    for (int s = 128; s > 0; s >>= 1) {
        if (t < s) { s1[t] += s1[t + s]; s2[t] += s2[t + s]; }
        __syncthreads();
    }
    if (t == 0) {
        double cnt  = (double)(BB * NPIX);
        double mean = s1[0] / cnt;
        double var  = s2[0] / cnt - mean * mean;
        g_mean[c] = (float)mean;
        g_rstd[c] = (float)(1.0 / sqrt(var + (double)EPSV));
    }
}

// ---------------- BN apply + residual + ReLU ----------------
__global__ void epilogue_k(const float* __restrict__ bn_w,
                           const float* __restrict__ bn_b,
                           float* __restrict__ out)
{
    int idx = blockIdx.x * blockDim.x + threadIdx.x;
    if (idx >= BB*CCH*NPIX) return;
    int c = (idx / NPIX) % CCH;
    float v = (g_o2[idx] - g_mean[c]) * g_rstd[c] * bn_w[c] + bn_b[c] + g_xp[idx];
    out[idx] = fmaxf(v, 0.f);
}

// ---------------- launch ----------------
extern "C" void kernel_launch(void* const* d_in, const int* in_sizes, int n_in,
                              void* d_out, int out_size)
{
    const float* x       = (const float*)d_in[0];
    const float* theta_w = (const float*)d_in[1];
    const float* phi_w   = (const float*)d_in[2];
    const float* g_w     = (const float*)d_in[3];
    const float* y_w     = (const float*)d_in[4];
    const float* bn_w    = (const float*)d_in[5];
    const float* bn_b    = (const float*)d_in[6];
    float* out = (float*)d_out;

    // resolve device-global addresses usable as kernel args
    float *p_thetaT, *p_phi, *p_gT;
    cudaGetSymbolAddress((void**)&p_thetaT, g_thetaT);
    cudaGetSymbolAddress((void**)&p_phi,    g_phi);
    cudaGetSymbolAddress((void**)&p_gT,     g_gT);

    // 1) pool
    {
        int n = BB*CCH*NPIX;
        pool_k<<<(n + 255) / 256, 256>>>(x);
    }

    // 2) projections
    {
        dim3 grid((NPIX + 255) / 256, C2H / 16, BB);
        proj_k<<<grid, 256>>>(theta_w, nullptr,  p_thetaT);
        proj_k<<<grid, 256>>>(phi_w,   p_phi,    nullptr);
        proj_k<<<grid, 256>>>(g_w,     nullptr,  p_gT);
    }

    // 3) scores
    {
        dim3 grid((NPIX + 255) / 256, (NPIX + 7) / 8, BB);
        score_k<<<grid, 256>>>();
    }

    // 4) softmax
    softmax_k<<<BB * NPIX, 256>>>();

    // 5) attention-value product
    {
        dim3 grid((NPIX + 3) / 4, BB);
        av_k<<<grid, 128>>>();
    }

    // 6) output projection (raw view)
    {
        dim3 grid((NPIX + 255) / 256, CCH / 16, BB);
        outproj_k<<<grid, 256>>>(y_w);
    }

    // 7) BN stats + 8) epilogue
    bnstats_k<<<CCH, 256>>>();
    {
        int n = BB*CCH*NPIX;
        epilogue_k<<<(n + 255) / 256, 256>>>(bn_w, bn_b, out);
    }
}

// round 3
// speedup vs baseline: 1.4991x; 1.4991x over previous
#include <cuda_runtime.h>
#include <math.h>

// ---------------- problem constants ----------------
#define BB    4
#define CCH   256
#define C2H   128
#define HO    63
#define WO    63
#define NPIX  (HO*WO)      // 3969
#define SLD   3972         // padded N-stride (mult of 4 -> float4 aligned rows)
#define HIN   128
#define WIN   128
#define EPSV  1e-5f
#define PAD   8192

// ---------------- scratch (device globals; zero-initialized) ----------------
__device__ float g_xp    [BB*CCH*SLD + PAD];            // (B,C,n) stride SLD — also residual
__device__ float g_thetaT[BB*NPIX*C2H + PAD];           // (B,N,C2)
__device__ float g_phi   [BB*C2H*SLD + PAD];            // (B,C2,n) stride SLD
__device__ float g_gT    [BB*NPIX*C2H + PAD];           // (B,N,C2)
__device__ float g_S     [(size_t)BB*NPIX*SLD + PAD];   // (B,N,m) stride SLD
__device__ float g_y     [BB*NPIX*C2H + PAD];           // (B,N,C2) contiguous
__device__ float g_o2    [BB*CCH*SLD + PAD];            // pre-BN (B,C,n) stride SLD
__device__ float g_mean  [CCH];
__device__ float g_rstd  [CCH];

// ---------------- 3x3/2 VALID max pool ----------------
__global__ void pool_k(const float* __restrict__ x) {
    int idx = blockIdx.x * blockDim.x + threadIdx.x;
    if (idx >= BB*CCH*NPIX) return;
    int n  = idx % NPIX;
    int bc = idx / NPIX;
    int ow = n % WO, oh = n / WO;
    const float* p = x + (size_t)bc * (HIN*WIN) + (oh*2) * WIN + (ow*2);
    float m = -INFINITY;
    #pragma unroll
    for (int i = 0; i < 3; i++) {
        m = fmaxf(m, p[i*WIN + 0]);
        m = fmaxf(m, p[i*WIN + 1]);
        m = fmaxf(m, p[i*WIN + 2]);
    }
    g_xp[(size_t)bc * SLD + n] = m;
}

// --------- fused 3-way projection: out[o,n] = sum_k W[o,k]*xp[k,n] ---------
// grid (63 n-tiles, 3 weights, BB). 256 thr. Tile 128o x 64n, micro 8x4, BK=32.
__global__ void proj3_k(const float* __restrict__ thW,
                        const float* __restrict__ phW,
                        const float* __restrict__ gW)
{
    __shared__ float sW[32][132];
    __shared__ float sX[32][68];
    int t  = threadIdx.x;
    int b  = blockIdx.z;
    int w  = blockIdx.y;               // 0=theta 1=phi 2=g
    int n0 = blockIdx.x * 64;
    const float* W = (w == 0) ? thW : (w == 1) ? phW : gW;
    const float* xb = g_xp + (size_t)b * CCH * SLD;

    int ty = t >> 4, tx = t & 15;
    int row = ty * 8, col = tx * 4;

    float acc[8][4];
    #pragma unroll
    for (int u = 0; u < 8; u++)
        #pragma unroll
        for (int v = 0; v < 4; v++) acc[u][v] = 0.f;

    for (int k0 = 0; k0 < CCH; k0 += 32) {
        #pragma unroll
        for (int it = 0; it < 4; it++) {               // W tile 128x32
            int o  = (t >> 3) + it * 32;
            int k4 = (t & 7) * 4;
            float4 v = *(const float4*)(W + (size_t)o * CCH + k0 + k4);
            sW[k4+0][o] = v.x; sW[k4+1][o] = v.y;
            sW[k4+2][o] = v.z; sW[k4+3][o] = v.w;
        }
        #pragma unroll
        for (int it = 0; it < 2; it++) {               // X tile 32x64
            int kk = (t >> 4) + it * 16;
            int j4 = (t & 15) * 4;
            float4 v = *(const float4*)(xb + (size_t)(k0 + kk) * SLD + n0 + j4);
            *(float4*)&sX[kk][j4] = v;
        }
        __syncthreads();

        #pragma unroll 4
        for (int kk = 0; kk < 32; kk++) {
            float4 a0 = *(const float4*)&sW[kk][row];
            float4 a1 = *(const float4*)&sW[kk][row + 4];
            float4 bx = *(const float4*)&sX[kk][col];
            float ra[8] = {a0.x,a0.y,a0.z,a0.w,a1.x,a1.y,a1.z,a1.w};
            float rb[4] = {bx.x,bx.y,bx.z,bx.w};
            #pragma unroll
            for (int u = 0; u < 8; u++)
                #pragma unroll
                for (int v = 0; v < 4; v++)
                    acc[u][v] = fmaf(ra[u], rb[v], acc[u][v]);
        }
        __syncthreads();
    }

    #pragma unroll
    for (int u = 0; u < 8; u++) {
        int o = row + u;
        #pragma unroll
        for (int v = 0; v < 4; v++) {
            int n = n0 + col + v;
            if (n >= NPIX) continue;
            if (w == 1)
                g_phi[(size_t)(b * C2H + o) * SLD + n] = acc[u][v];
            else {
                float* dst = (w == 0) ? g_thetaT : g_gT;
                dst[(size_t)(b * NPIX + n) * C2H + o] = acc[u][v];
            }
        }
    }
}

// ------- scores: S[n,m] = sum_c thetaT[n,c]*phi[c,m]; tile 128x128, BK=32 -------
__global__ void score_k() {
    __shared__ float sTh[32][132];
    __shared__ float sPh[32][132];
    int t  = threadIdx.x;
    int b  = blockIdx.z;
    int n0 = blockIdx.y * 128;
    int m0 = blockIdx.x * 128;
    const float* thb = g_thetaT + (size_t)b * NPIX * C2H;
    const float* phb = g_phi    + (size_t)b * C2H * SLD;

    int ty = t >> 4, tx = t & 15;
    int row = ty * 8, col = tx * 8;

    float acc[8][8];
    #pragma unroll
    for (int u = 0; u < 8; u++)
        #pragma unroll
        for (int v = 0; v < 8; v++) acc[u][v] = 0.f;

    for (int k0 = 0; k0 < C2H; k0 += 32) {
        #pragma unroll
        for (int it = 0; it < 4; it++) {               // theta 128n x 32k
            int i  = (t >> 3) + it * 32;
            int k4 = (t & 7) * 4;
            int n  = n0 + i;
            float4 v = make_float4(0.f, 0.f, 0.f, 0.f);
            if (n < NPIX) v = *(const float4*)(thb + (size_t)n * C2H + k0 + k4);
            sTh[k4+0][i] = v.x; sTh[k4+1][i] = v.y;
            sTh[k4+2][i] = v.z; sTh[k4+3][i] = v.w;
        }
        #pragma unroll
        for (int it = 0; it < 4; it++) {               // phi 32k x 128m
            int kk = (t >> 5) + it * 8;
            int j4 = (t & 31) * 4;
            float4 v = *(const float4*)(phb + (size_t)(k0 + kk) * SLD + m0 + j4);
            *(float4*)&sPh[kk][j4] = v;
        }
        __syncthreads();

        #pragma unroll 4
        for (int kk = 0; kk < 32; kk++) {
            float4 a0 = *(const float4*)&sTh[kk][row];
            float4 a1 = *(const float4*)&sTh[kk][row + 4];
            float4 b0 = *(const float4*)&sPh[kk][col];
            float4 b1 = *(const float4*)&sPh[kk][col + 4];
            float ra[8] = {a0.x,a0.y,a0.z,a0.w,a1.x,a1.y,a1.z,a1.w};
            float rb[8] = {b0.x,b0.y,b0.z,b0.w,b1.x,b1.y,b1.z,b1.w};
            #pragma unroll
            for (int u = 0; u < 8; u++)
                #pragma unroll
                for (int v = 0; v < 8; v++)
                    acc[u][v] = fmaf(ra[u], rb[v], acc[u][v]);
        }
        __syncthreads();
    }

    float* Sb = g_S + (size_t)b * NPIX * SLD;
    #pragma unroll
    for (int u = 0; u < 8; u++) {
        int n = n0 + row + u;
        if (n >= NPIX) continue;
        #pragma unroll
        for (int v = 0; v < 8; v++) {
            int m = m0 + col + v;
            if (m < NPIX) Sb[(size_t)n * SLD + m] = acc[u][v];
        }
    }
}

// ---------------- 2-pass register softmax, 512 thr/row ----------------
__global__ void softmax_k() {
    size_t r = blockIdx.x;                       // B*N rows; layout (b*N+n)*SLD
    float* Srow = g_S + r * SLD;
    int t = threadIdx.x;                         // 512
    __shared__ float sm[16], ss[16];

    float v[8];
    float mx = -INFINITY;
    #pragma unroll
    for (int i = 0; i < 8; i++) {
        int m = t + i * 512;
        v[i] = (m < NPIX) ? Srow[m] : -INFINITY;
        mx = fmaxf(mx, v[i]);
    }
    #pragma unroll
    for (int o = 16; o; o >>= 1) mx = fmaxf(mx, __shfl_xor_sync(~0u, mx, o));
    if ((t & 31) == 0) sm[t >> 5] = mx;
    __syncthreads();
    float bm = sm[0];
    #pragma unroll
    for (int w = 1; w < 16; w++) bm = fmaxf(bm, sm[w]);

    float sum = 0.f;
    #pragma unroll
    for (int i = 0; i < 8; i++) { v[i] = expf(v[i] - bm); sum += v[i]; }
    #pragma unroll
    for (int o = 16; o; o >>= 1) sum += __shfl_xor_sync(~0u, sum, o);
    if ((t & 31) == 0) ss[t >> 5] = sum;
    __syncthreads();
    float bs = 0.f;
    #pragma unroll
    for (int w = 0; w < 16; w++) bs += ss[w];
    float inv = 1.f / bs;

    #pragma unroll
    for (int i = 0; i < 8; i++) {
        int m = t + i * 512;
        if (m < NPIX) Srow[m] = v[i] * inv;
    }
}

// ------- AV: y[n,c] = sum_m f[n,m]*gT[m,c]; tile 64n x 128c, BK=32 -------
__global__ void av_k() {
    __shared__ float sF[32][68];
    __shared__ float sG[32][132];
    int t  = threadIdx.x;
    int b  = blockIdx.y;
    int n0 = blockIdx.x * 64;
    const float* Sb  = g_S  + (size_t)b * NPIX * SLD;
    const float* gTb = g_gT + (size_t)b * NPIX * C2H;

    int ty = t >> 4, tx = t & 15;
    int row = ty * 4, col = tx * 8;

    float acc[4][8];
    #pragma unroll
    for (int u = 0; u < 4; u++)
        #pragma unroll
        for (int v = 0; v < 8; v++) acc[u][v] = 0.f;

    for (int k0 = 0; k0 < NPIX; k0 += 32) {
        #pragma unroll
        for (int it = 0; it < 2; it++) {               // f tile 64n x 32k
            int i  = (t >> 3) + it * 32;
            int k4 = (t & 7) * 4;
            int n  = n0 + i;
            float4 v = make_float4(0.f, 0.f, 0.f, 0.f);
            if (n < NPIX && (k0 + k4 + 3) < SLD)       // S[n, 3969..3971] == 0
                v = *(const float4*)(Sb + (size_t)n * SLD + k0 + k4);
            sF[k4+0][i] = v.x; sF[k4+1][i] = v.y;
            sF[k4+2][i] = v.z; sF[k4+3][i] = v.w;
        }
        #pragma unroll
        for (int it = 0; it < 4; it++) {               // g tile 32k x 128c
            int kk = (t >> 5) + it * 8;
            int j4 = (t & 31) * 4;                     // k-tail pairs with sF==0
            float4 v = *(const float4*)(gTb + (size_t)(k0 + kk) * C2H + j4);
            *(float4*)&sG[kk][j4] = v;
        }
        __syncthreads();

        #pragma unroll 4
        for (int kk = 0; kk < 32; kk++) {
            float4 a  = *(const float4*)&sF[kk][row];
            float4 b0 = *(const float4*)&sG[kk][col];
            float4 b1 = *(const float4*)&sG[kk][col + 4];
            float ra[4] = {a.x,a.y,a.z,a.w};
            float rb[8] = {b0.x,b0.y,b0.z,b0.w,b1.x,b1.y,b1.z,b1.w};
            #pragma unroll
            for (int u = 0; u < 4; u++)
                #pragma unroll
                for (int v = 0; v < 8; v++)
                    acc[u][v] = fmaf(ra[u], rb[v], acc[u][v]);
        }
        __syncthreads();
    }

    #pragma unroll
    for (int u = 0; u < 4; u++) {
        int n = n0 + row + u;
        if (n >= NPIX) continue;
        float* dst = g_y + (size_t)(b * NPIX + n) * C2H + col;
        *(float4*)dst       = make_float4(acc[u][0], acc[u][1], acc[u][2], acc[u][3]);
        *(float4*)(dst + 4) = make_float4(acc[u][4], acc[u][5], acc[u][6], acc[u][7]);
    }
}

// ---- out proj: o2[o,m] = sum_c y_w[o,c]*yflat[c*NPIX+m] (raw view) ----
// grid (63 m-tiles, 2 o-tiles, BB). Tile 128o x 64m, micro 8x4, BK=32 (K=128).
__global__ void outproj_k(const float* __restrict__ y_w) {
    __shared__ float sW[32][132];
    __shared__ float sX[32][68];
    int t  = threadIdx.x;
    int b  = blockIdx.z;
    int o0 = blockIdx.y * 128;
    int m0 = blockIdx.x * 64;
    const float* yb = g_y + (size_t)b * NPIX * C2H;    // flat, viewed (C2, NPIX)

    int ty = t >> 4, tx = t & 15;
    int row = ty * 8, col = tx * 4;

    float acc[8][4];
    #pragma unroll
    for (int u = 0; u < 8; u++)
        #pragma unroll
        for (int v = 0; v < 4; v++) acc[u][v] = 0.f;

    for (int k0 = 0; k0 < C2H; k0 += 32) {
        #pragma unroll
        for (int it = 0; it < 4; it++) {               // W 128o x 32k
            int o  = (t >> 3) + it * 32;
            int k4 = (t & 7) * 4;
            float4 v = *(const float4*)(y_w + (size_t)(o0 + o) * C2H + k0 + k4);
            sW[k4+0][o] = v.x; sW[k4+1][o] = v.y;
            sW[k4+2][o] = v.z; sW[k4+3][o] = v.w;
        }
        #pragma unroll
        for (int it = 0; it < 8; it++) {               // yview 32k x 64m (stride 3969 -> scalar)
            int idx = t + it * 256;
            int kk = idx >> 6, j = idx & 63;
            sX[kk][j] = yb[(size_t)(k0 + kk) * NPIX + m0 + j];   // PAD covers tail
        }
        __syncthreads();

        #pragma unroll 4
        for (int kk = 0; kk < 32; kk++) {
            float4 a0 = *(const float4*)&sW[kk][row];
            float4 a1 = *(const float4*)&sW[kk][row + 4];
            float4 bx = *(const float4*)&sX[kk][col];
            float ra[8] = {a0.x,a0.y,a0.z,a0.w,a1.x,a1.y,a1.z,a1.w};
            float rb[4] = {bx.x,bx.y,bx.z,bx.w};
            #pragma unroll
            for (int u = 0; u < 8; u++)
                #pragma unroll
                for (int v = 0; v < 4; v++)
                    acc[u][v] = fmaf(ra[u], rb[v], acc[u][v]);
        }
        __syncthreads();
    }

    #pragma unroll
    for (int u = 0; u < 8; u++) {
        int o = o0 + row + u;
        #pragma unroll
        for (int v = 0; v < 4; v++) {
            int m = m0 + col + v;
            if (m < NPIX)
                g_o2[(size_t)(b * CCH + o) * SLD + m] = acc[u][v];
        }
    }
}

// ---------------- BN stats (per channel over B,N) ----------------
__global__ void bnstats_k() {
    int c = blockIdx.x;
    int t = threadIdx.x;  // 256
    __shared__ double s1[256];
    __shared__ double s2[256];
    double a = 0.0, b2 = 0.0;
    for (int b = 0; b < BB; b++) {
        const float* p = g_o2 + (size_t)(b * CCH + c) * SLD;
        for (int m = t; m < NPIX; m += 256) {
            double v = (double)p[m];
            a  += v;
            b2 += v * v;
        }
    }
    s1[t] = a; s2[t] = b2; __syncthreads();
    for (int s = 128; s > 0; s >>= 1) {
        if (t < s) { s1[t] += s1[t + s]; s2[t] += s2[t + s]; }
        __syncthreads();
    }
    if (t == 0) {
        double cnt  = (double)(BB * NPIX);
        double mean = s1[0] / cnt;
        double var  = s2[0] / cnt - mean * mean;
        g_mean[c] = (float)mean;
        g_rstd[c] = (float)(1.0 / sqrt(var + (double)EPSV));
    }
}

// ---------------- BN apply + residual + ReLU ----------------
__global__ void epilogue_k(const float* __restrict__ bn_w,
                           const float* __restrict__ bn_b,
                           float* __restrict__ out)
{
    int idx = blockIdx.x * blockDim.x + threadIdx.x;
    if (idx >= BB*CCH*NPIX) return;
    int n  = idx % NPIX;
    int bc = idx / NPIX;
    int c  = bc % CCH;
    size_t off = (size_t)bc * SLD + n;
    float v = (g_o2[off] - g_mean[c]) * g_rstd[c] * bn_w[c] + bn_b[c] + g_xp[off];
    out[idx] = fmaxf(v, 0.f);
}

// ---------------- launch ----------------
extern "C" void kernel_launch(void* const* d_in, const int* in_sizes, int n_in,
                              void* d_out, int out_size)
{
    const float* x       = (const float*)d_in[0];
    const float* theta_w = (const float*)d_in[1];
    const float* phi_w   = (const float*)d_in[2];
    const float* g_w     = (const float*)d_in[3];
    const float* y_w     = (const float*)d_in[4];
    const float* bn_w    = (const float*)d_in[5];
    const float* bn_b    = (const float*)d_in[6];
    float* out = (float*)d_out;

    { int n = BB*CCH*NPIX; pool_k<<<(n + 255) / 256, 256>>>(x); }

    { dim3 grid(63, 3, BB); proj3_k<<<grid, 256>>>(theta_w, phi_w, g_w); }

    { dim3 grid((NPIX + 127) / 128, (NPIX + 127) / 128, BB);
      score_k<<<grid, 256>>>(); }

    softmax_k<<<BB * NPIX, 512>>>();

    { dim3 grid((NPIX + 63) / 64, BB); av_k<<<grid, 256>>>(); }

    { dim3 grid(63, 2, BB); outproj_k<<<grid, 256>>>(y_w); }

    bnstats_k<<<CCH, 256>>>();

    { int n = BB*CCH*NPIX; epilogue_k<<<(n + 255) / 256, 256>>>(bn_w, bn_b, out); }
}

// round 4
// speedup vs baseline: 2.0034x; 1.3364x over previous
#include <cuda_runtime.h>
#include <cuda_bf16.h>
#include <math.h>
#include <stdint.h>

// ---------------- problem constants ----------------
#define BB    4
#define CCH   256
#define C2H   128
#define HO    63
#define WO    63
#define NPIX  (HO*WO)      // 3969
#define SLD   3972         // padded fp32 N-stride
#define MLD   4000         // padded bf16 K-stride for AV (mult of 32)
#define HIN   128
#define WIN   128
#define EPSV  1e-5f
#define PAD   8192

// ---------------- scratch (device globals; zero-initialized) ----------------
__device__ __align__(256) float g_xp [BB*CCH*SLD + PAD];              // pooled (B,C,n)
__device__ __align__(256) float g_S  [(size_t)BB*NPIX*SLD + PAD];     // scores fp32
__device__ __align__(256) float g_y  [BB*NPIX*C2H + PAD];             // (B,N,C2)
__device__ __align__(256) float g_o2 [BB*CCH*SLD + PAD];              // pre-BN
__device__ float g_mean[CCH];
__device__ float g_rstd[CCH];

// bf16 split operands
__device__ __align__(256) __nv_bfloat16 g_th_hi[BB*NPIX*C2H + PAD];   // theta (B,N,C2)
__device__ __align__(256) __nv_bfloat16 g_th_lo[BB*NPIX*C2H + PAD];
__device__ __align__(256) __nv_bfloat16 g_ph_hi[BB*NPIX*C2H + PAD];   // phi   (B,M,C2)
__device__ __align__(256) __nv_bfloat16 g_ph_lo[BB*NPIX*C2H + PAD];
__device__ __align__(256) __nv_bfloat16 g_gc_hi[BB*C2H*MLD + PAD];    // g     (B,C2,MLD) tail=0
__device__ __align__(256) __nv_bfloat16 g_gc_lo[BB*C2H*MLD + PAD];
__device__ __align__(256) __nv_bfloat16 g_f_hi[(size_t)BB*NPIX*MLD + PAD]; // softmax out, tail=0
__device__ __align__(256) __nv_bfloat16 g_f_lo[(size_t)BB*NPIX*MLD + PAD];

// ---------------- 3x3/2 VALID max pool ----------------
__global__ void pool_k(const float* __restrict__ x) {
    int idx = blockIdx.x * blockDim.x + threadIdx.x;
    if (idx >= BB*CCH*NPIX) return;
    int n  = idx % NPIX;
    int bc = idx / NPIX;
    int ow = n % WO, oh = n / WO;
    const float* p = x + (size_t)bc * (HIN*WIN) + (oh*2) * WIN + (ow*2);
    float m = -INFINITY;
    #pragma unroll
    for (int i = 0; i < 3; i++) {
        m = fmaxf(m, p[i*WIN + 0]);
        m = fmaxf(m, p[i*WIN + 1]);
        m = fmaxf(m, p[i*WIN + 2]);
    }
    g_xp[(size_t)bc * SLD + n] = m;
}

// --------- fused 3-way projection, bf16 hi/lo epilogue ---------
// out[o,n] = sum_k W[o,k]*xp[k,n].  grid (63 n-tiles, 3 weights, BB), 256 thr.
__global__ void proj3_k(const float* __restrict__ thW,
                        const float* __restrict__ phW,
                        const float* __restrict__ gW)
{
    __shared__ float sW[32][132];
    __shared__ float sX[32][68];
    int t  = threadIdx.x;
    int b  = blockIdx.z;
    int w  = blockIdx.y;               // 0=theta 1=phi 2=g
    int n0 = blockIdx.x * 64;
    const float* W = (w == 0) ? thW : (w == 1) ? phW : gW;
    const float* xb = g_xp + (size_t)b * CCH * SLD;

    int ty = t >> 4, tx = t & 15;
    int row = ty * 8, col = tx * 4;

    float acc[8][4];
    #pragma unroll
    for (int u = 0; u < 8; u++)
        #pragma unroll
        for (int v = 0; v < 4; v++) acc[u][v] = 0.f;

    for (int k0 = 0; k0 < CCH; k0 += 32) {
        #pragma unroll
        for (int it = 0; it < 4; it++) {
            int o  = (t >> 3) + it * 32;
            int k4 = (t & 7) * 4;
            float4 v = *(const float4*)(W + (size_t)o * CCH + k0 + k4);
            sW[k4+0][o] = v.x; sW[k4+1][o] = v.y;
            sW[k4+2][o] = v.z; sW[k4+3][o] = v.w;
        }
        #pragma unroll
        for (int it = 0; it < 2; it++) {
            int kk = (t >> 4) + it * 16;
            int j4 = (t & 15) * 4;
            float4 v = *(const float4*)(xb + (size_t)(k0 + kk) * SLD + n0 + j4);
            *(float4*)&sX[kk][j4] = v;
        }
        __syncthreads();

        #pragma unroll 4
        for (int kk = 0; kk < 32; kk++) {
            float4 a0 = *(const float4*)&sW[kk][row];
            float4 a1 = *(const float4*)&sW[kk][row + 4];
            float4 bx = *(const float4*)&sX[kk][col];
            float ra[8] = {a0.x,a0.y,a0.z,a0.w,a1.x,a1.y,a1.z,a1.w};
            float rb[4] = {bx.x,bx.y,bx.z,bx.w};
            #pragma unroll
            for (int u = 0; u < 8; u++)
                #pragma unroll
                for (int v = 0; v < 4; v++)
                    acc[u][v] = fmaf(ra[u], rb[v], acc[u][v]);
        }
        __syncthreads();
    }

    #pragma unroll
    for (int u = 0; u < 8; u++) {
        int o = row + u;
        #pragma unroll
        for (int v = 0; v < 4; v++) {
            int n = n0 + col + v;
            if (n >= NPIX) continue;
            float a = acc[u][v];
            __nv_bfloat16 hi = __float2bfloat16(a);
            __nv_bfloat16 lo = __float2bfloat16(a - __bfloat162float(hi));
            if (w == 0) {
                size_t idx = (size_t)(b * NPIX + n) * C2H + o;
                g_th_hi[idx] = hi; g_th_lo[idx] = lo;
            } else if (w == 1) {
                size_t idx = (size_t)(b * NPIX + n) * C2H + o;
                g_ph_hi[idx] = hi; g_ph_lo[idx] = lo;
            } else {
                size_t idx = (size_t)(b * C2H + o) * MLD + n;
                g_gc_hi[idx] = hi; g_gc_lo[idx] = lo;
            }
        }
    }
}

// -------- generic NT split-bf16 MMA: C[i,j] = sum_k A[i,k]*B[j,k] --------
// A,B: bf16 hi/lo, K-fast. 3 phases: (Ahi,Bhi),(Ahi,Blo),(Alo,Bhi).
// CTA tile 128i x 128j, BK=32, 256 thr (8 warps 4i x 2j; warp 32i x 64j).
#define MMA16816(d, a, b)                                                   \
    asm volatile("mma.sync.aligned.m16n8k16.row.col.f32.bf16.bf16.f32 "     \
                 "{%0,%1,%2,%3},{%4,%5,%6,%7},{%8,%9},{%0,%1,%2,%3};"       \
                 : "+f"(d[0]), "+f"(d[1]), "+f"(d[2]), "+f"(d[3])           \
                 : "r"(a[0]), "r"(a[1]), "r"(a[2]), "r"(a[3]),              \
                   "r"(b[0]), "r"(b[1]))

__global__ __launch_bounds__(256) void mmant_k(
        const __nv_bfloat16* __restrict__ Ahi,
        const __nv_bfloat16* __restrict__ Alo,
        const __nv_bfloat16* __restrict__ Bhi,
        const __nv_bfloat16* __restrict__ Blo,
        float* __restrict__ Cout,
        int I, int J, int lda, int ldb, int ldc, int ksteps,
        size_t strA, size_t strB, size_t strC)
{
    __shared__ __align__(16) __nv_bfloat16 sA[128][40];
    __shared__ __align__(16) __nv_bfloat16 sB[128][40];
    int t = threadIdx.x, lane = t & 31, w = t >> 5;
    int b = blockIdx.z;
    int i0 = blockIdx.y * 128, j0 = blockIdx.x * 128;
    const __nv_bfloat16* AhiB = Ahi + (size_t)b * strA;
    const __nv_bfloat16* AloB = Alo + (size_t)b * strA;
    const __nv_bfloat16* BhiB = Bhi + (size_t)b * strB;
    const __nv_bfloat16* BloB = Blo + (size_t)b * strB;
    float* Cb = Cout + (size_t)b * strC;

    int wi = (w & 3) * 32, wj = (w >> 2) * 64;
    int g  = lane >> 2, tg = lane & 3;

    float acc[2][8][4];
    #pragma unroll
    for (int fi = 0; fi < 2; fi++)
        #pragma unroll
        for (int fj = 0; fj < 8; fj++)
            #pragma unroll
            for (int e = 0; e < 4; e++) acc[fi][fj][e] = 0.f;

    int lrow = t >> 1, lh = (t & 1) * 16;
    const uint4 Z = make_uint4(0u, 0u, 0u, 0u);

    for (int ph = 0; ph < 3; ph++) {
        const __nv_bfloat16* Ap = (ph == 2) ? AloB : AhiB;
        const __nv_bfloat16* Bp = (ph == 1) ? BloB : BhiB;
        for (int s = 0; s < ksteps; s++) {
            int k0 = s * 32;
            // global -> smem
            {
                uint4 v0 = Z, v1 = Z;
                int gi = i0 + lrow;
                if (gi < I) {
                    const uint4* p = (const uint4*)(Ap + (size_t)gi * lda + k0 + lh);
                    v0 = p[0]; v1 = p[1];
                }
                *(uint4*)&sA[lrow][lh]     = v0;
                *(uint4*)&sA[lrow][lh + 8] = v1;
                v0 = Z; v1 = Z;
                int gj = j0 + lrow;
                if (gj < J) {
                    const uint4* p = (const uint4*)(Bp + (size_t)gj * ldb + k0 + lh);
                    v0 = p[0]; v1 = p[1];
                }
                *(uint4*)&sB[lrow][lh]     = v0;
                *(uint4*)&sB[lrow][lh + 8] = v1;
            }
            __syncthreads();

            #pragma unroll
            for (int kk = 0; kk < 32; kk += 16) {
                uint32_t a[2][4], bb[8][2];
                #pragma unroll
                for (int fi = 0; fi < 2; fi++) {
                    int r = wi + fi * 16 + g;
                    a[fi][0] = *(const uint32_t*)&sA[r    ][kk + tg*2    ];
                    a[fi][1] = *(const uint32_t*)&sA[r + 8][kk + tg*2    ];
                    a[fi][2] = *(const uint32_t*)&sA[r    ][kk + tg*2 + 8];
                    a[fi][3] = *(const uint32_t*)&sA[r + 8][kk + tg*2 + 8];
                }
                #pragma unroll
                for (int fj = 0; fj < 8; fj++) {
                    int c = wj + fj * 8 + g;
                    bb[fj][0] = *(const uint32_t*)&sB[c][kk + tg*2    ];
                    bb[fj][1] = *(const uint32_t*)&sB[c][kk + tg*2 + 8];
                }
                #pragma unroll
                for (int fi = 0; fi < 2; fi++)
                    #pragma unroll
                    for (int fj = 0; fj < 8; fj++)
                        MMA16816(acc[fi][fj], a[fi], bb[fj]);
            }
            __syncthreads();
        }
    }

    // epilogue
    #pragma unroll
    for (int fi = 0; fi < 2; fi++) {
        int r0 = i0 + wi + fi * 16 + g;
        #pragma unroll
        for (int fj = 0; fj < 8; fj++) {
            int c0 = j0 + wj + fj * 8 + tg * 2;
            if (c0 >= J) continue;
            bool c1ok = (c0 + 1) < J;
            if (r0 < I) {
                Cb[(size_t)r0 * ldc + c0] = acc[fi][fj][0];
                if (c1ok) Cb[(size_t)r0 * ldc + c0 + 1] = acc[fi][fj][1];
            }
            if (r0 + 8 < I) {
                Cb[(size_t)(r0 + 8) * ldc + c0] = acc[fi][fj][2];
                if (c1ok) Cb[(size_t)(r0 + 8) * ldc + c0 + 1] = acc[fi][fj][3];
            }
        }
    }
}

// ------- softmax: fp32 S row -> normalized, emitted as bf16 hi/lo -------
__global__ void softmax_k() {
    size_t r = blockIdx.x;                       // b*NPIX + n
    float* Srow = g_S + r * SLD;
    __nv_bfloat16* Fh = g_f_hi + r * MLD;
    __nv_bfloat16* Fl = g_f_lo + r * MLD;
    int t = threadIdx.x;                         // 512
    __shared__ float sm[16], ss[16];

    float v[8];
    float mx = -INFINITY;
    #pragma unroll
    for (int i = 0; i < 8; i++) {
        int m = t + i * 512;
        v[i] = (m < NPIX) ? Srow[m] : -INFINITY;
        mx = fmaxf(mx, v[i]);
    }
    #pragma unroll
    for (int o = 16; o; o >>= 1) mx = fmaxf(mx, __shfl_xor_sync(~0u, mx, o));
    if ((t & 31) == 0) sm[t >> 5] = mx;
    __syncthreads();
    float bm = sm[0];
    #pragma unroll
    for (int ww = 1; ww < 16; ww++) bm = fmaxf(bm, sm[ww]);

    float sum = 0.f;
    #pragma unroll
    for (int i = 0; i < 8; i++) { v[i] = expf(v[i] - bm); sum += v[i]; }
    #pragma unroll
    for (int o = 16; o; o >>= 1) sum += __shfl_xor_sync(~0u, sum, o);
    if ((t & 31) == 0) ss[t >> 5] = sum;
    __syncthreads();
    float bs = 0.f;
    #pragma unroll
    for (int ww = 0; ww < 16; ww++) bs += ss[ww];
    float inv = 1.f / bs;

    #pragma unroll
    for (int i = 0; i < 8; i++) {
        int m = t + i * 512;
        if (m < NPIX) {
            float f = v[i] * inv;
            __nv_bfloat16 hi = __float2bfloat16(f);
            Fh[m] = hi;
            Fl[m] = __float2bfloat16(f - __bfloat162float(hi));
        }
    }
}

// ---- out proj: o2[o,m] = sum_c y_w[o,c]*yflat[c*NPIX+m] (raw view) ----
__global__ void outproj_k(const float* __restrict__ y_w) {
    __shared__ float sW[32][132];
    __shared__ float sX[32][68];
    int t  = threadIdx.x;
    int b  = blockIdx.z;
    int o0 = blockIdx.y * 128;
    int m0 = blockIdx.x * 64;
    const float* yb = g_y + (size_t)b * NPIX * C2H;    // flat, viewed (C2, NPIX)

    int ty = t >> 4, tx = t & 15;
    int row = ty * 8, col = tx * 4;

    float acc[8][4];
    #pragma unroll
    for (int u = 0; u < 8; u++)
        #pragma unroll
        for (int v = 0; v < 4; v++) acc[u][v] = 0.f;

    for (int k0 = 0; k0 < C2H; k0 += 32) {
        #pragma unroll
        for (int it = 0; it < 4; it++) {
            int o  = (t >> 3) + it * 32;
            int k4 = (t & 7) * 4;
            float4 v = *(const float4*)(y_w + (size_t)(o0 + o) * C2H + k0 + k4);
            sW[k4+0][o] = v.x; sW[k4+1][o] = v.y;
            sW[k4+2][o] = v.z; sW[k4+3][o] = v.w;
        }
        #pragma unroll
        for (int it = 0; it < 8; it++) {
            int idx = t + it * 256;
            int kk = idx >> 6, j = idx & 63;
            sX[kk][j] = yb[(size_t)(k0 + kk) * NPIX + m0 + j];   // PAD covers tail
        }
        __syncthreads();

        #pragma unroll 4
        for (int kk = 0; kk < 32; kk++) {
            float4 a0 = *(const float4*)&sW[kk][row];
            float4 a1 = *(const float4*)&sW[kk][row + 4];
            float4 bx = *(const float4*)&sX[kk][col];
            float ra[8] = {a0.x,a0.y,a0.z,a0.w,a1.x,a1.y,a1.z,a1.w};
            float rb[4] = {bx.x,bx.y,bx.z,bx.w};
            #pragma unroll
            for (int u = 0; u < 8; u++)
                #pragma unroll
                for (int v = 0; v < 4; v++)
                    acc[u][v] = fmaf(ra[u], rb[v], acc[u][v]);
        }
        __syncthreads();
    }

    #pragma unroll
    for (int u = 0; u < 8; u++) {
        int o = o0 + row + u;
        #pragma unroll
        for (int v = 0; v < 4; v++) {
            int m = m0 + col + v;
            if (m < NPIX)
                g_o2[(size_t)(b * CCH + o) * SLD + m] = acc[u][v];
        }
    }
}

// ---------------- BN stats ----------------
__global__ void bnstats_k() {
    int c = blockIdx.x;
    int t = threadIdx.x;
    __shared__ double s1[256];
    __shared__ double s2[256];
    double a = 0.0, b2 = 0.0;
    for (int b = 0; b < BB; b++) {
        const float* p = g_o2 + (size_t)(b * CCH + c) * SLD;
        for (int m = t; m < NPIX; m += 256) {
            double v = (double)p[m];
            a  += v;
            b2 += v * v;
        }
    }
    s1[t] = a; s2[t] = b2; __syncthreads();
    for (int s = 128; s > 0; s >>= 1) {
        if (t < s) { s1[t] += s1[t + s]; s2[t] += s2[t + s]; }
        __syncthreads();
    }
    if (t == 0) {
        double cnt  = (double)(BB * NPIX);
        double mean = s1[0] / cnt;
        double var  = s2[0] / cnt - mean * mean;
        g_mean[c] = (float)mean;
        g_rstd[c] = (float)(1.0 / sqrt(var + (double)EPSV));
    }
}

// ---------------- BN apply + residual + ReLU ----------------
__global__ void epilogue_k(const float* __restrict__ bn_w,
                           const float* __restrict__ bn_b,
                           float* __restrict__ out)
{
    int idx = blockIdx.x * blockDim.x + threadIdx.x;
    if (idx >= BB*CCH*NPIX) return;
    int n  = idx % NPIX;
    int bc = idx / NPIX;
    int c  = bc % CCH;
    size_t off = (size_t)bc * SLD + n;
    float v = (g_o2[off] - g_mean[c]) * g_rstd[c] * bn_w[c] + bn_b[c] + g_xp[off];
    out[idx] = fmaxf(v, 0.f);
}

// ---------------- launch ----------------
extern "C" void kernel_launch(void* const* d_in, const int* in_sizes, int n_in,
                              void* d_out, int out_size)
{
    const float* x       = (const float*)d_in[0];
    const float* theta_w = (const float*)d_in[1];
    const float* phi_w   = (const float*)d_in[2];
    const float* g_w     = (const float*)d_in[3];
    const float* y_w     = (const float*)d_in[4];
    const float* bn_w    = (const float*)d_in[5];
    const float* bn_b    = (const float*)d_in[6];
    float* out = (float*)d_out;

    __nv_bfloat16 *p_th_hi, *p_th_lo, *p_ph_hi, *p_ph_lo;
    __nv_bfloat16 *p_gc_hi, *p_gc_lo, *p_f_hi, *p_f_lo;
    float *p_S, *p_y;
    cudaGetSymbolAddress((void**)&p_th_hi, g_th_hi);
    cudaGetSymbolAddress((void**)&p_th_lo, g_th_lo);
    cudaGetSymbolAddress((void**)&p_ph_hi, g_ph_hi);
    cudaGetSymbolAddress((void**)&p_ph_lo, g_ph_lo);
    cudaGetSymbolAddress((void**)&p_gc_hi, g_gc_hi);
    cudaGetSymbolAddress((void**)&p_gc_lo, g_gc_lo);
    cudaGetSymbolAddress((void**)&p_f_hi,  g_f_hi);
    cudaGetSymbolAddress((void**)&p_f_lo,  g_f_lo);
    cudaGetSymbolAddress((void**)&p_S,     g_S);
    cudaGetSymbolAddress((void**)&p_y,     g_y);

    { int n = BB*CCH*NPIX; pool_k<<<(n + 255) / 256, 256>>>(x); }

    { dim3 grid(63, 3, BB); proj3_k<<<grid, 256>>>(theta_w, phi_w, g_w); }

    // scores: S = theta @ phi^T  (I=J=NPIX, K=128)
    { dim3 grid(32, 32, BB);
      mmant_k<<<grid, 256>>>(p_th_hi, p_th_lo, p_ph_hi, p_ph_lo, p_S,
                             NPIX, NPIX, C2H, C2H, SLD, 4,
                             (size_t)NPIX*C2H, (size_t)NPIX*C2H, (size_t)NPIX*SLD); }

    softmax_k<<<BB * NPIX, 512>>>();

    // AV: y = f @ g^T  (I=NPIX, J=128, K=MLD=4000, zero-padded tail)
    { dim3 grid(1, 32, BB);
      mmant_k<<<grid, 256>>>(p_f_hi, p_f_lo, p_gc_hi, p_gc_lo, p_y,
                             NPIX, C2H, MLD, MLD, C2H, MLD/32,
                             (size_t)NPIX*MLD, (size_t)C2H*MLD, (size_t)NPIX*C2H); }

    { dim3 grid(63, 2, BB); outproj_k<<<grid, 256>>>(y_w); }

    bnstats_k<<<CCH, 256>>>();

    { int n = BB*CCH*NPIX; epilogue_k<<<(n + 255) / 256, 256>>>(bn_w, bn_b, out); }
}

// round 5
// speedup vs baseline: 2.6981x; 1.3467x over previous
#include <cuda_runtime.h>
#include <cuda_bf16.h>
#include <math.h>
#include <stdint.h>

// ---------------- problem constants ----------------
#define BB    4
#define CCH   256
#define C2H   128
#define HO    63
#define WO    63
#define NPIX  (HO*WO)      // 3969
#define SLD   3972         // padded fp32 N-stride
#define MLD   4000         // padded bf16 K-stride for AV (mult of 32)
#define HIN   128
#define WIN   128
#define EPSV  1e-5f
#define PAD   8192

// ---------------- scratch (device globals; zero-initialized) ----------------
__device__ __align__(256) float g_xp [BB*CCH*SLD + PAD];              // pooled (B,C,n)
__device__ __align__(256) float g_S  [(size_t)BB*NPIX*SLD + PAD];     // scores fp32
__device__ __align__(256) float g_y  [BB*NPIX*C2H + PAD];             // (B,N,C2)
__device__ __align__(256) float g_o2 [BB*CCH*SLD + PAD];              // pre-BN
__device__ float g_mean[CCH];
__device__ float g_rstd[CCH];

// bf16 split operands
__device__ __align__(256) __nv_bfloat16 g_th_hi[BB*NPIX*C2H + PAD];   // theta (B,N,C2)
__device__ __align__(256) __nv_bfloat16 g_th_lo[BB*NPIX*C2H + PAD];
__device__ __align__(256) __nv_bfloat16 g_ph_hi[BB*NPIX*C2H + PAD];   // phi   (B,M,C2)
__device__ __align__(256) __nv_bfloat16 g_ph_lo[BB*NPIX*C2H + PAD];
__device__ __align__(256) __nv_bfloat16 g_gc_hi[BB*C2H*MLD + PAD];    // g     (B,C2,MLD) tail=0
__device__ __align__(256) __nv_bfloat16 g_gc_lo[BB*C2H*MLD + PAD];
__device__ __align__(256) __nv_bfloat16 g_f_hi[(size_t)BB*NPIX*MLD + PAD]; // softmax out, tail=0
__device__ __align__(256) __nv_bfloat16 g_f_lo[(size_t)BB*NPIX*MLD + PAD];

// ---------------- 3x3/2 VALID max pool ----------------
__global__ void pool_k(const float* __restrict__ x) {
    int idx = blockIdx.x * blockDim.x + threadIdx.x;
    if (idx >= BB*CCH*NPIX) return;
    int n  = idx % NPIX;
    int bc = idx / NPIX;
    int ow = n % WO, oh = n / WO;
    const float* p = x + (size_t)bc * (HIN*WIN) + (oh*2) * WIN + (ow*2);
    float m = -INFINITY;
    #pragma unroll
    for (int i = 0; i < 3; i++) {
        m = fmaxf(m, p[i*WIN + 0]);
        m = fmaxf(m, p[i*WIN + 1]);
        m = fmaxf(m, p[i*WIN + 2]);
    }
    g_xp[(size_t)bc * SLD + n] = m;
}

// --------- fused 3-way projection, bf16 hi/lo epilogue ---------
__global__ void proj3_k(const float* __restrict__ thW,
                        const float* __restrict__ phW,
                        const float* __restrict__ gW)
{
    __shared__ float sW[32][132];
    __shared__ float sX[32][68];
    int t  = threadIdx.x;
    int b  = blockIdx.z;
    int w  = blockIdx.y;               // 0=theta 1=phi 2=g
    int n0 = blockIdx.x * 64;
    const float* W = (w == 0) ? thW : (w == 1) ? phW : gW;
    const float* xb = g_xp + (size_t)b * CCH * SLD;

    int ty = t >> 4, tx = t & 15;
    int row = ty * 8, col = tx * 4;

    float acc[8][4];
    #pragma unroll
    for (int u = 0; u < 8; u++)
        #pragma unroll
        for (int v = 0; v < 4; v++) acc[u][v] = 0.f;

    for (int k0 = 0; k0 < CCH; k0 += 32) {
        #pragma unroll
        for (int it = 0; it < 4; it++) {
            int o  = (t >> 3) + it * 32;
            int k4 = (t & 7) * 4;
            float4 v = *(const float4*)(W + (size_t)o * CCH + k0 + k4);
            sW[k4+0][o] = v.x; sW[k4+1][o] = v.y;
            sW[k4+2][o] = v.z; sW[k4+3][o] = v.w;
        }
        #pragma unroll
        for (int it = 0; it < 2; it++) {
            int kk = (t >> 4) + it * 16;
            int j4 = (t & 15) * 4;
            float4 v = *(const float4*)(xb + (size_t)(k0 + kk) * SLD + n0 + j4);
            *(float4*)&sX[kk][j4] = v;
        }
        __syncthreads();

        #pragma unroll 4
        for (int kk = 0; kk < 32; kk++) {
            float4 a0 = *(const float4*)&sW[kk][row];
            float4 a1 = *(const float4*)&sW[kk][row + 4];
            float4 bx = *(const float4*)&sX[kk][col];
            float ra[8] = {a0.x,a0.y,a0.z,a0.w,a1.x,a1.y,a1.z,a1.w};
            float rb[4] = {bx.x,bx.y,bx.z,bx.w};
            #pragma unroll
            for (int u = 0; u < 8; u++)
                #pragma unroll
                for (int v = 0; v < 4; v++)
                    acc[u][v] = fmaf(ra[u], rb[v], acc[u][v]);
        }
        __syncthreads();
    }

    #pragma unroll
    for (int u = 0; u < 8; u++) {
        int o = row + u;
        #pragma unroll
        for (int v = 0; v < 4; v++) {
            int n = n0 + col + v;
            if (n >= NPIX) continue;
            float a = acc[u][v];
            __nv_bfloat16 hi = __float2bfloat16(a);
            __nv_bfloat16 lo = __float2bfloat16(a - __bfloat162float(hi));
            if (w == 0) {
                size_t idx = (size_t)(b * NPIX + n) * C2H + o;
                g_th_hi[idx] = hi; g_th_lo[idx] = lo;
            } else if (w == 1) {
                size_t idx = (size_t)(b * NPIX + n) * C2H + o;
                g_ph_hi[idx] = hi; g_ph_lo[idx] = lo;
            } else {
                size_t idx = (size_t)(b * C2H + o) * MLD + n;
                g_gc_hi[idx] = hi; g_gc_lo[idx] = lo;
            }
        }
    }
}

// -------- generic NT split-bf16 MMA: C[i,j] = sum_k A[i,k]*B[j,k] --------
// ldmatrix fragment loads + cp.async 2-stage pipeline.
#define MMA16816(d, a, b)                                                   \
    asm volatile("mma.sync.aligned.m16n8k16.row.col.f32.bf16.bf16.f32 "     \
                 "{%0,%1,%2,%3},{%4,%5,%6,%7},{%8,%9},{%0,%1,%2,%3};"       \
                 : "+f"(d[0]), "+f"(d[1]), "+f"(d[2]), "+f"(d[3])           \
                 : "r"(a[0]), "r"(a[1]), "r"(a[2]), "r"(a[3]),              \
                   "r"(b[0]), "r"(b[1]))

#define LDSM4(r, p)                                                         \
    asm volatile("ldmatrix.sync.aligned.m8n8.x4.shared.b16 "                \
                 "{%0,%1,%2,%3}, [%4];"                                     \
                 : "=r"((r)[0]), "=r"((r)[1]), "=r"((r)[2]), "=r"((r)[3])   \
                 : "r"(p))

#define CPASYNC16(dst, src, nbytes)                                         \
    asm volatile("cp.async.cg.shared.global [%0], [%1], 16, %2;"            \
                 :: "r"(dst), "l"(src), "r"(nbytes) : "memory")

__global__ __launch_bounds__(256) void mmant_k(
        const __nv_bfloat16* __restrict__ Ahi,
        const __nv_bfloat16* __restrict__ Alo,
        const __nv_bfloat16* __restrict__ Bhi,
        const __nv_bfloat16* __restrict__ Blo,
        float* __restrict__ Cout,
        int I, int J, int lda, int ldb, int ldc, int ksteps,
        size_t strA, size_t strB, size_t strC)
{
    __shared__ __align__(16) __nv_bfloat16 sA[2][128][40];
    __shared__ __align__(16) __nv_bfloat16 sB[2][128][40];
    int t = threadIdx.x, lane = t & 31, w = t >> 5;
    int b = blockIdx.z;
    int i0 = blockIdx.y * 128, j0 = blockIdx.x * 128;
    const __nv_bfloat16* AhiB = Ahi + (size_t)b * strA;
    const __nv_bfloat16* AloB = Alo + (size_t)b * strA;
    const __nv_bfloat16* BhiB = Bhi + (size_t)b * strB;
    const __nv_bfloat16* BloB = Blo + (size_t)b * strB;
    float* Cb = Cout + (size_t)b * strC;

    int wi = (w & 3) * 32, wj = (w >> 2) * 64;
    int g  = lane >> 2, tg = lane & 3;

    // per-thread cp.async assignments: 2 chunks of 16B per operand tile
    int c0id = t, c1id = t + 256;                // chunk = row*4 + quarter
    int ar0 = c0id >> 2, ac0 = (c0id & 3) * 8;
    int ar1 = c1id >> 2, ac1 = (c1id & 3) * 8;

    // ldmatrix per-lane source offsets
    int a_ro = (lane & 7) + ((lane >> 3) & 1) * 8;  // row within 16
    int a_co = (lane >> 4) * 8;                     // 0 or 8
    int b_ro = (lane & 7) + ((lane >> 4) & 1) * 8;  // row within 16
    int b_co = ((lane >> 3) & 1) * 8;               // 0 or 8

    float acc[2][8][4];
    #pragma unroll
    for (int fi = 0; fi < 2; fi++)
        #pragma unroll
        for (int fj = 0; fj < 8; fj++)
            #pragma unroll
            for (int e = 0; e < 4; e++) acc[fi][fj][e] = 0.f;

    int total = 3 * ksteps;

    auto issue = [&](int s) {
        int ph = s / ksteps;
        int k0 = (s - ph * ksteps) * 32;
        int buf = s & 1;
        const __nv_bfloat16* Ap = (ph == 2) ? AloB : AhiB;
        const __nv_bfloat16* Bp = (ph == 1) ? BloB : BhiB;
        // A chunks
        {
            uint32_t d = (uint32_t)__cvta_generic_to_shared(&sA[buf][ar0][ac0]);
            const void* sp = Ap + (size_t)(i0 + ar0) * lda + k0 + ac0;
            CPASYNC16(d, sp, (i0 + ar0 < I) ? 16 : 0);
            d = (uint32_t)__cvta_generic_to_shared(&sA[buf][ar1][ac1]);
            sp = Ap + (size_t)(i0 + ar1) * lda + k0 + ac1;
            CPASYNC16(d, sp, (i0 + ar1 < I) ? 16 : 0);
        }
        // B chunks
        {
            uint32_t d = (uint32_t)__cvta_generic_to_shared(&sB[buf][ar0][ac0]);
            const void* sp = Bp + (size_t)(j0 + ar0) * ldb + k0 + ac0;
            CPASYNC16(d, sp, (j0 + ar0 < J) ? 16 : 0);
            d = (uint32_t)__cvta_generic_to_shared(&sB[buf][ar1][ac1]);
            sp = Bp + (size_t)(j0 + ar1) * ldb + k0 + ac1;
            CPASYNC16(d, sp, (j0 + ar1 < J) ? 16 : 0);
        }
        asm volatile("cp.async.commit_group;" ::: "memory");
    };

    issue(0);

    for (int s = 0; s < total; s++) {
        if (s + 1 < total) issue(s + 1);
        else asm volatile("cp.async.commit_group;" ::: "memory");
        asm volatile("cp.async.wait_group 1;" ::: "memory");
        __syncthreads();

        int buf = s & 1;
        #pragma unroll
        for (int kk = 0; kk < 32; kk += 16) {
            uint32_t a[2][4];
            #pragma unroll
            for (int fi = 0; fi < 2; fi++) {
                uint32_t p = (uint32_t)__cvta_generic_to_shared(
                    &sA[buf][wi + fi * 16 + a_ro][kk + a_co]);
                LDSM4(a[fi], p);
            }
            uint32_t bb[8][2];
            #pragma unroll
            for (int jp = 0; jp < 4; jp++) {
                uint32_t r[4];
                uint32_t p = (uint32_t)__cvta_generic_to_shared(
                    &sB[buf][wj + jp * 16 + b_ro][kk + b_co]);
                LDSM4(r, p);
                bb[2*jp  ][0] = r[0]; bb[2*jp  ][1] = r[1];
                bb[2*jp+1][0] = r[2]; bb[2*jp+1][1] = r[3];
            }
            #pragma unroll
            for (int fi = 0; fi < 2; fi++)
                #pragma unroll
                for (int fj = 0; fj < 8; fj++)
                    MMA16816(acc[fi][fj], a[fi], bb[fj]);
        }
        __syncthreads();
    }

    // epilogue
    #pragma unroll
    for (int fi = 0; fi < 2; fi++) {
        int r0 = i0 + wi + fi * 16 + g;
        #pragma unroll
        for (int fj = 0; fj < 8; fj++) {
            int c0 = j0 + wj + fj * 8 + tg * 2;
            if (c0 >= J) continue;
            bool c1ok = (c0 + 1) < J;
            if (r0 < I) {
                Cb[(size_t)r0 * ldc + c0] = acc[fi][fj][0];
                if (c1ok) Cb[(size_t)r0 * ldc + c0 + 1] = acc[fi][fj][1];
            }
            if (r0 + 8 < I) {
                Cb[(size_t)(r0 + 8) * ldc + c0] = acc[fi][fj][2];
                if (c1ok) Cb[(size_t)(r0 + 8) * ldc + c0 + 1] = acc[fi][fj][3];
            }
        }
    }
}

// ------- softmax: fp32 S row -> normalized, emitted as bf16 hi/lo -------
__global__ void softmax_k() {
    size_t r = blockIdx.x;                       // b*NPIX + n
    float* Srow = g_S + r * SLD;
    __nv_bfloat16* Fh = g_f_hi + r * MLD;
    __nv_bfloat16* Fl = g_f_lo + r * MLD;
    int t = threadIdx.x;                         // 512
    __shared__ float sm[16], ss[16];

    float v[8];
    float mx = -INFINITY;
    #pragma unroll
    for (int i = 0; i < 8; i++) {
        int m = t + i * 512;
        v[i] = (m < NPIX) ? Srow[m] : -INFINITY;
        mx = fmaxf(mx, v[i]);
    }
    #pragma unroll
    for (int o = 16; o; o >>= 1) mx = fmaxf(mx, __shfl_xor_sync(~0u, mx, o));
    if ((t & 31) == 0) sm[t >> 5] = mx;
    __syncthreads();
    float bm = sm[0];
    #pragma unroll
    for (int ww = 1; ww < 16; ww++) bm = fmaxf(bm, sm[ww]);

    float sum = 0.f;
    #pragma unroll
    for (int i = 0; i < 8; i++) { v[i] = expf(v[i] - bm); sum += v[i]; }
    #pragma unroll
    for (int o = 16; o; o >>= 1) sum += __shfl_xor_sync(~0u, sum, o);
    if ((t & 31) == 0) ss[t >> 5] = sum;
    __syncthreads();
    float bs = 0.f;
    #pragma unroll
    for (int ww = 0; ww < 16; ww++) bs += ss[ww];
    float inv = 1.f / bs;

    #pragma unroll
    for (int i = 0; i < 8; i++) {
        int m = t + i * 512;
        if (m < NPIX) {
            float f = v[i] * inv;
            __nv_bfloat16 hi = __float2bfloat16(f);
            Fh[m] = hi;
            Fl[m] = __float2bfloat16(f - __bfloat162float(hi));
        }
    }
}

// ---- out proj: o2[o,m] = sum_c y_w[o,c]*yflat[c*NPIX+m] (raw view) ----
__global__ void outproj_k(const float* __restrict__ y_w) {
    __shared__ float sW[32][132];
    __shared__ float sX[32][68];
    int t  = threadIdx.x;
    int b  = blockIdx.z;
    int o0 = blockIdx.y * 128;
    int m0 = blockIdx.x * 64;
    const float* yb = g_y + (size_t)b * NPIX * C2H;    // flat, viewed (C2, NPIX)

    int ty = t >> 4, tx = t & 15;
    int row = ty * 8, col = tx * 4;

    float acc[8][4];
    #pragma unroll
    for (int u = 0; u < 8; u++)
        #pragma unroll
        for (int v = 0; v < 4; v++) acc[u][v] = 0.f;

    for (int k0 = 0; k0 < C2H; k0 += 32) {
        #pragma unroll
        for (int it = 0; it < 4; it++) {
            int o  = (t >> 3) + it * 32;
            int k4 = (t & 7) * 4;
            float4 v = *(const float4*)(y_w + (size_t)(o0 + o) * C2H + k0 + k4);
            sW[k4+0][o] = v.x; sW[k4+1][o] = v.y;
            sW[k4+2][o] = v.z; sW[k4+3][o] = v.w;
        }
        #pragma unroll
        for (int it = 0; it < 8; it++) {
            int idx = t + it * 256;
            int kk = idx >> 6, j = idx & 63;
            sX[kk][j] = yb[(size_t)(k0 + kk) * NPIX + m0 + j];   // PAD covers tail
        }
        __syncthreads();

        #pragma unroll 4
        for (int kk = 0; kk < 32; kk++) {
            float4 a0 = *(const float4*)&sW[kk][row];
            float4 a1 = *(const float4*)&sW[kk][row + 4];
            float4 bx = *(const float4*)&sX[kk][col];
            float ra[8] = {a0.x,a0.y,a0.z,a0.w,a1.x,a1.y,a1.z,a1.w};
            float rb[4] = {bx.x,bx.y,bx.z,bx.w};
            #pragma unroll
            for (int u = 0; u < 8; u++)
                #pragma unroll
                for (int v = 0; v < 4; v++)
                    acc[u][v] = fmaf(ra[u], rb[v], acc[u][v]);
        }
        __syncthreads();
    }

    #pragma unroll
    for (int u = 0; u < 8; u++) {
        int o = o0 + row + u;
        #pragma unroll
        for (int v = 0; v < 4; v++) {
            int m = m0 + col + v;
            if (m < NPIX)
                g_o2[(size_t)(b * CCH + o) * SLD + m] = acc[u][v];
        }
    }
}

// ---------------- BN stats ----------------
__global__ void bnstats_k() {
    int c = blockIdx.x;
    int t = threadIdx.x;
    __shared__ double s1[256];
    __shared__ double s2[256];
    double a = 0.0, b2 = 0.0;
    for (int b = 0; b < BB; b++) {
        const float* p = g_o2 + (size_t)(b * CCH + c) * SLD;
        for (int m = t; m < NPIX; m += 256) {
            double v = (double)p[m];
            a  += v;
            b2 += v * v;
        }
    }
    s1[t] = a; s2[t] = b2; __syncthreads();
    for (int s = 128; s > 0; s >>= 1) {
        if (t < s) { s1[t] += s1[t + s]; s2[t] += s2[t + s]; }
        __syncthreads();
    }
    if (t == 0) {
        double cnt  = (double)(BB * NPIX);
        double mean = s1[0] / cnt;
        double var  = s2[0] / cnt - mean * mean;
        g_mean[c] = (float)mean;
        g_rstd[c] = (float)(1.0 / sqrt(var + (double)EPSV));
    }
}

// ---------------- BN apply + residual + ReLU ----------------
__global__ void epilogue_k(const float* __restrict__ bn_w,
                           const float* __restrict__ bn_b,
                           float* __restrict__ out)
{
    int idx = blockIdx.x * blockDim.x + threadIdx.x;
    if (idx >= BB*CCH*NPIX) return;
    int n  = idx % NPIX;
    int bc = idx / NPIX;
    int c  = bc % CCH;
    size_t off = (size_t)bc * SLD + n;
    float v = (g_o2[off] - g_mean[c]) * g_rstd[c] * bn_w[c] + bn_b[c] + g_xp[off];
    out[idx] = fmaxf(v, 0.f);
}

// ---------------- launch ----------------
extern "C" void kernel_launch(void* const* d_in, const int* in_sizes, int n_in,
                              void* d_out, int out_size)
{
    const float* x       = (const float*)d_in[0];
    const float* theta_w = (const float*)d_in[1];
    const float* phi_w   = (const float*)d_in[2];
    const float* g_w     = (const float*)d_in[3];
    const float* y_w     = (const float*)d_in[4];
    const float* bn_w    = (const float*)d_in[5];
    const float* bn_b    = (const float*)d_in[6];
    float* out = (float*)d_out;

    __nv_bfloat16 *p_th_hi, *p_th_lo, *p_ph_hi, *p_ph_lo;
    __nv_bfloat16 *p_gc_hi, *p_gc_lo, *p_f_hi, *p_f_lo;
    float *p_S, *p_y;
    cudaGetSymbolAddress((void**)&p_th_hi, g_th_hi);
    cudaGetSymbolAddress((void**)&p_th_lo, g_th_lo);
    cudaGetSymbolAddress((void**)&p_ph_hi, g_ph_hi);
    cudaGetSymbolAddress((void**)&p_ph_lo, g_ph_lo);
    cudaGetSymbolAddress((void**)&p_gc_hi, g_gc_hi);
    cudaGetSymbolAddress((void**)&p_gc_lo, g_gc_lo);
    cudaGetSymbolAddress((void**)&p_f_hi,  g_f_hi);
    cudaGetSymbolAddress((void**)&p_f_lo,  g_f_lo);
    cudaGetSymbolAddress((void**)&p_S,     g_S);
    cudaGetSymbolAddress((void**)&p_y,     g_y);

    { int n = BB*CCH*NPIX; pool_k<<<(n + 255) / 256, 256>>>(x); }

    { dim3 grid(63, 3, BB); proj3_k<<<grid, 256>>>(theta_w, phi_w, g_w); }

    // scores: S = theta @ phi^T  (I=J=NPIX, K=128)
    { dim3 grid(32, 32, BB);
      mmant_k<<<grid, 256>>>(p_th_hi, p_th_lo, p_ph_hi, p_ph_lo, p_S,
                             NPIX, NPIX, C2H, C2H, SLD, 4,
                             (size_t)NPIX*C2H, (size_t)NPIX*C2H, (size_t)NPIX*SLD); }

    softmax_k<<<BB * NPIX, 512>>>();

    // AV: y = f @ g^T  (I=NPIX, J=128, K=MLD=4000, zero-padded tail)
    { dim3 grid(1, 32, BB);
      mmant_k<<<grid, 256>>>(p_f_hi, p_f_lo, p_gc_hi, p_gc_lo, p_y,
                             NPIX, C2H, MLD, MLD, C2H, MLD/32,
                             (size_t)NPIX*MLD, (size_t)C2H*MLD, (size_t)NPIX*C2H); }

    { dim3 grid(63, 2, BB); outproj_k<<<grid, 256>>>(y_w); }

    bnstats_k<<<CCH, 256>>>();

    { int n = BB*CCH*NPIX; epilogue_k<<<(n + 255) / 256, 256>>>(bn_w, bn_b, out); }
}

// round 7
// speedup vs baseline: 4.0395x; 1.4971x over previous
#include <cuda_runtime.h>
#include <cuda_bf16.h>
#include <math.h>
#include <stdint.h>

// ---------------- problem constants ----------------
#define BB    4
#define CCH   256
#define C2H   128
#define HO    63
#define WO    63
#define NPIX  (HO*WO)      // 3969
#define XLD   3972         // padded fp32 stride for xp/o2
#define MLD   4096         // bf16 m-stride for g (mult of 64)
#define HIN   128
#define WIN   128
#define EPSV  1e-5f
#define PAD   32768

// ---------------- scratch (device globals; zero-initialized) ----------------
__device__ __align__(256) float g_xp [BB*CCH*XLD + PAD];              // pooled (B,C,n)
__device__ __align__(256) float g_y  [BB*NPIX*C2H + PAD];             // (B,N,C2)
__device__ __align__(256) float g_o2 [BB*CCH*XLD + PAD];              // pre-BN
__device__ float g_mean[CCH];
__device__ float g_rstd[CCH];

// bf16 split operands
__device__ __align__(256) __nv_bfloat16 g_th_hi[BB*NPIX*C2H + PAD];   // theta (B,N,C2)
__device__ __align__(256) __nv_bfloat16 g_th_lo[BB*NPIX*C2H + PAD];
__device__ __align__(256) __nv_bfloat16 g_ph_hi[BB*NPIX*C2H + PAD];   // phi   (B,M,C2)
__device__ __align__(256) __nv_bfloat16 g_ph_lo[BB*NPIX*C2H + PAD];
__device__ __align__(256) __nv_bfloat16 g_gc_hi[BB*C2H*MLD + PAD];    // g     (B,C2,MLD) tail=0
__device__ __align__(256) __nv_bfloat16 g_gc_lo[BB*C2H*MLD + PAD];

// ---------------- 3x3/2 VALID max pool ----------------
__global__ void pool_k(const float* __restrict__ x) {
    int idx = blockIdx.x * blockDim.x + threadIdx.x;
    if (idx >= BB*CCH*NPIX) return;
    int n  = idx % NPIX;
    int bc = idx / NPIX;
    int ow = n % WO, oh = n / WO;
    const float* p = x + (size_t)bc * (HIN*WIN) + (oh*2) * WIN + (ow*2);
    float m = -INFINITY;
    #pragma unroll
    for (int i = 0; i < 3; i++) {
        m = fmaxf(m, p[i*WIN + 0]);
        m = fmaxf(m, p[i*WIN + 1]);
        m = fmaxf(m, p[i*WIN + 2]);
    }
    g_xp[(size_t)bc * XLD + n] = m;
}

// --------- fused 3-way projection, bf16 hi/lo epilogue ---------
__global__ void proj3_k(const float* __restrict__ thW,
                        const float* __restrict__ phW,
                        const float* __restrict__ gW)
{
    __shared__ float sW[32][132];
    __shared__ float sX[32][68];
    int t  = threadIdx.x;
    int b  = blockIdx.z;
    int w  = blockIdx.y;               // 0=theta 1=phi 2=g
    int n0 = blockIdx.x * 64;
    const float* W = (w == 0) ? thW : (w == 1) ? phW : gW;
    const float* xb = g_xp + (size_t)b * CCH * XLD;

    int ty = t >> 4, tx = t & 15;
    int row = ty * 8, col = tx * 4;

    float acc[8][4];
    #pragma unroll
    for (int u = 0; u < 8; u++)
        #pragma unroll
        for (int v = 0; v < 4; v++) acc[u][v] = 0.f;

    for (int k0 = 0; k0 < CCH; k0 += 32) {
        #pragma unroll
        for (int it = 0; it < 4; it++) {
            int o  = (t >> 3) + it * 32;
            int k4 = (t & 7) * 4;
            float4 v = *(const float4*)(W + (size_t)o * CCH + k0 + k4);
            sW[k4+0][o] = v.x; sW[k4+1][o] = v.y;
            sW[k4+2][o] = v.z; sW[k4+3][o] = v.w;
        }
        #pragma unroll
        for (int it = 0; it < 2; it++) {
            int kk = (t >> 4) + it * 16;
            int j4 = (t & 15) * 4;
            float4 v = *(const float4*)(xb + (size_t)(k0 + kk) * XLD + n0 + j4);
            *(float4*)&sX[kk][j4] = v;
        }
        __syncthreads();

        #pragma unroll 4
        for (int kk = 0; kk < 32; kk++) {
            float4 a0 = *(const float4*)&sW[kk][row];
            float4 a1 = *(const float4*)&sW[kk][row + 4];
            float4 bx = *(const float4*)&sX[kk][col];
            float ra[8] = {a0.x,a0.y,a0.z,a0.w,a1.x,a1.y,a1.z,a1.w};
            float rb[4] = {bx.x,bx.y,bx.z,bx.w};
            #pragma unroll
            for (int u = 0; u < 8; u++)
                #pragma unroll
                for (int v = 0; v < 4; v++)
                    acc[u][v] = fmaf(ra[u], rb[v], acc[u][v]);
        }
        __syncthreads();
    }

    #pragma unroll
    for (int u = 0; u < 8; u++) {
        int o = row + u;
        #pragma unroll
        for (int v = 0; v < 4; v++) {
            int n = n0 + col + v;
            if (n >= NPIX) continue;
            float a = acc[u][v];
            __nv_bfloat16 hi = __float2bfloat16(a);
            __nv_bfloat16 lo = __float2bfloat16(a - __bfloat162float(hi));
            if (w == 0) {
                size_t idx = (size_t)(b * NPIX + n) * C2H + o;
                g_th_hi[idx] = hi; g_th_lo[idx] = lo;
            } else if (w == 1) {
                size_t idx = (size_t)(b * NPIX + n) * C2H + o;
                g_ph_hi[idx] = hi; g_ph_lo[idx] = lo;
            } else {
                size_t idx = (size_t)(b * C2H + o) * MLD + n;
                g_gc_hi[idx] = hi; g_gc_lo[idx] = lo;
            }
        }
    }
}

// ================= fused flash attention (split-bf16 mma.sync) =================
#define TM   64           // m-tile
#define NT   63           // ceil(3969/64)
#define THRB 272          // theta/phi smem row stride bytes (136 bf16)
#define GRB  144          // g smem row stride bytes (72 bf16)
#define SM_TH_HI 0
#define SM_TH_LO 34816
#define SM_STG   69632
#define ST_PH_HI 0
#define ST_PH_LO 17408
#define ST_G_HI  34816
#define ST_G_LO  53248
#define STG_SZ   71680
#define SMEM_FLASH (SM_STG + 2*STG_SZ)   // 212992

#define MMA16816(d, a, b)                                                   \
    asm volatile("mma.sync.aligned.m16n8k16.row.col.f32.bf16.bf16.f32 "     \
                 "{%0,%1,%2,%3},{%4,%5,%6,%7},{%8,%9},{%0,%1,%2,%3};"       \
                 : "+f"((d)[0]), "+f"((d)[1]), "+f"((d)[2]), "+f"((d)[3])   \
                 : "r"((a)[0]), "r"((a)[1]), "r"((a)[2]), "r"((a)[3]),      \
                   "r"((b)[0]), "r"((b)[1]))

#define LDSM4(r, p)                                                         \
    asm volatile("ldmatrix.sync.aligned.m8n8.x4.shared.b16 "                \
                 "{%0,%1,%2,%3}, [%4];"                                     \
                 : "=r"((r)[0]), "=r"((r)[1]), "=r"((r)[2]), "=r"((r)[3])   \
                 : "r"(p))

#define CPA16(dst, src)                                                     \
    asm volatile("cp.async.cg.shared.global [%0], [%1], 16;"                \
                 :: "r"(dst), "l"(src) : "memory")

__device__ __forceinline__ uint32_t pk_bf2(float x, float y) {
    __nv_bfloat162 h = __floats2bfloat162_rn(x, y);
    return *(uint32_t*)&h;
}

__global__ __launch_bounds__(256, 1) void flash_k() {
    extern __shared__ __align__(256) char smem[];
    uint32_t sb = (uint32_t)__cvta_generic_to_shared(smem);
    int t = threadIdx.x, lane = t & 31, wid = t >> 5;
    int b = blockIdx.y;
    int q0 = blockIdx.x * 128;

    // ---- theta tile (hi+lo) -> smem, resident ----
    #pragma unroll
    for (int it = 0; it < 8; it++) {
        int cid = t + it * 256;
        int r = cid >> 4, q = cid & 15;
        size_t off = (size_t)(b * NPIX + q0 + r) * C2H + q * 8;
        CPA16(sb + SM_TH_HI + r * THRB + q * 16, g_th_hi + off);
        CPA16(sb + SM_TH_LO + r * THRB + q * 16, g_th_lo + off);
    }
    asm volatile("cp.async.commit_group;" ::: "memory");

    auto issue_stage = [&](int s) {
        int m0 = s * TM;
        uint32_t stg = sb + SM_STG + (s & 1) * STG_SZ;
        #pragma unroll
        for (int it = 0; it < 4; it++) {
            int cid = t + it * 256;
            int r = cid >> 4, q = cid & 15;
            size_t off = (size_t)(b * NPIX + m0 + r) * C2H + q * 8;
            CPA16(stg + ST_PH_HI + r * THRB + q * 16, g_ph_hi + off);
            CPA16(stg + ST_PH_LO + r * THRB + q * 16, g_ph_lo + off);
        }
        #pragma unroll
        for (int it = 0; it < 4; it++) {
            int cid = t + it * 256;
            int r = cid >> 3, q = cid & 7;
            size_t off = (size_t)(b * C2H + r) * MLD + m0 + q * 8;
            CPA16(stg + ST_G_HI + r * GRB + q * 16, g_gc_hi + off);
            CPA16(stg + ST_G_LO + r * GRB + q * 16, g_gc_lo + off);
        }
        asm volatile("cp.async.commit_group;" ::: "memory");
    };
    issue_stage(0);

    // lane fragment geometry
    int gq = lane >> 2, tg = lane & 3;
    int a_ro = (lane & 7) + ((lane >> 3) & 1) * 8;
    int a_co = (lane >> 4) * 8;
    int b_ro = (lane & 7) + ((lane >> 4) & 1) * 8;
    int b_co = ((lane >> 3) & 1) * 8;

    uint32_t thA_hi = sb + SM_TH_HI + (wid * 16 + a_ro) * THRB + a_co * 2;
    uint32_t thA_lo = sb + SM_TH_LO + (wid * 16 + a_ro) * THRB + a_co * 2;

    float m0r = -INFINITY, m1r = -INFINITY;
    float l0r = 0.f, l1r = 0.f;
    float accy[16][4];
    #pragma unroll
    for (int fc = 0; fc < 16; fc++)
        #pragma unroll
        for (int e = 0; e < 4; e++) accy[fc][e] = 0.f;

    for (int itr = 0; itr < NT; itr++) {
        if (itr + 1 < NT) {
            issue_stage(itr + 1);
            asm volatile("cp.async.wait_group 1;" ::: "memory");
        } else {
            asm volatile("cp.async.wait_group 0;" ::: "memory");
        }
        __syncthreads();
        uint32_t stg = sb + SM_STG + (itr & 1) * STG_SZ;

        // ---- score: S[16q x 64m] per warp, 3 split phases ----
        float s[8][4];
        #pragma unroll
        for (int fj = 0; fj < 8; fj++)
            #pragma unroll
            for (int e = 0; e < 4; e++) s[fj][e] = 0.f;

        #pragma unroll
        for (int ph = 0; ph < 3; ph++) {
            uint32_t ab = (ph == 2) ? thA_lo : thA_hi;
            uint32_t bb = stg + ((ph == 1) ? ST_PH_LO : ST_PH_HI)
                        + b_ro * THRB + b_co * 2;
            #pragma unroll
            for (int k16 = 0; k16 < 8; k16++) {
                uint32_t a[4];
                LDSM4(a, ab + k16 * 32);
                #pragma unroll
                for (int mb = 0; mb < 4; mb++) {
                    uint32_t r[4];
                    LDSM4(r, bb + mb * 16 * THRB + k16 * 32);
                    MMA16816(s[2*mb],     a, r);
                    MMA16816(s[2*mb + 1], a, r + 2);
                }
            }
        }

        // ---- mask tail ----
        if (itr == NT - 1) {
            int mbase = itr * TM;
            #pragma unroll
            for (int fj = 0; fj < 8; fj++) {
                int c = mbase + fj * 8 + tg * 2;
                if (c     >= NPIX) { s[fj][0] = -INFINITY; s[fj][2] = -INFINITY; }
                if (c + 1 >= NPIX) { s[fj][1] = -INFINITY; s[fj][3] = -INFINITY; }
            }
        }

        // ---- online softmax ----
        float mx0 = -INFINITY, mx1 = -INFINITY;
        #pragma unroll
        for (int fj = 0; fj < 8; fj++) {
            mx0 = fmaxf(mx0, fmaxf(s[fj][0], s[fj][1]));
            mx1 = fmaxf(mx1, fmaxf(s[fj][2], s[fj][3]));
        }
        mx0 = fmaxf(mx0, __shfl_xor_sync(~0u, mx0, 1));
        mx0 = fmaxf(mx0, __shfl_xor_sync(~0u, mx0, 2));
        mx1 = fmaxf(mx1, __shfl_xor_sync(~0u, mx1, 1));
        mx1 = fmaxf(mx1, __shfl_xor_sync(~0u, mx1, 2));

        float mn0 = fmaxf(m0r, mx0), mn1 = fmaxf(m1r, mx1);
        float sc0 = expf(m0r - mn0), sc1 = expf(m1r - mn1);
        m0r = mn0; m1r = mn1;

        uint32_t phh0[8], phh1[8], phl0[8], phl1[8];
        float sum0 = 0.f, sum1 = 0.f;
        #pragma unroll
        for (int fj = 0; fj < 8; fj++) {
            float p0 = expf(s[fj][0] - mn0);
            float p1 = expf(s[fj][1] - mn0);
            float p2 = expf(s[fj][2] - mn1);
            float p3 = expf(s[fj][3] - mn1);
            sum0 += p0 + p1; sum1 += p2 + p3;
            float h0 = __bfloat162float(__float2bfloat16(p0));
            float h1 = __bfloat162float(__float2bfloat16(p1));
            float h2 = __bfloat162float(__float2bfloat16(p2));
            float h3 = __bfloat162float(__float2bfloat16(p3));
            phh0[fj] = pk_bf2(h0, h1);
            phh1[fj] = pk_bf2(h2, h3);
            phl0[fj] = pk_bf2(p0 - h0, p1 - h1);
            phl1[fj] = pk_bf2(p2 - h2, p3 - h3);
        }
        sum0 += __shfl_xor_sync(~0u, sum0, 1);
        sum0 += __shfl_xor_sync(~0u, sum0, 2);
        sum1 += __shfl_xor_sync(~0u, sum1, 1);
        sum1 += __shfl_xor_sync(~0u, sum1, 2);
        l0r = l0r * sc0 + sum0;
        l1r = l1r * sc1 + sum1;

        #pragma unroll
        for (int fc = 0; fc < 16; fc++) {
            accy[fc][0] *= sc0; accy[fc][1] *= sc0;
            accy[fc][2] *= sc1; accy[fc][3] *= sc1;
        }

        // ---- AV: y += P @ G^T (3 split phases, P from registers) ----
        #pragma unroll
        for (int ph = 0; ph < 3; ph++) {
            uint32_t gb = stg + ((ph == 1) ? ST_G_LO : ST_G_HI)
                        + b_ro * GRB + b_co * 2;
            uint32_t* pa0 = (ph == 2) ? phl0 : phh0;
            uint32_t* pa1 = (ph == 2) ? phl1 : phh1;
            #pragma unroll
            for (int kw = 0; kw < 4; kw++) {
                uint32_t a[4] = { pa0[2*kw], pa1[2*kw], pa0[2*kw+1], pa1[2*kw+1] };
                #pragma unroll
                for (int fc16 = 0; fc16 < 8; fc16++) {
                    uint32_t r[4];
                    LDSM4(r, gb + fc16 * 16 * GRB + kw * 32);
                    MMA16816(accy[2*fc16],     a, r);
                    MMA16816(accy[2*fc16 + 1], a, r + 2);
                }
            }
        }
        __syncthreads();
    }

    // ---- finalize: y /= l, store (B,N,C2) ----
    float inv0 = 1.f / l0r, inv1 = 1.f / l1r;
    int row0 = q0 + wid * 16 + gq;
    int row1 = row0 + 8;
    #pragma unroll
    for (int fc = 0; fc < 16; fc++) {
        int col = fc * 8 + tg * 2;
        if (row0 < NPIX) {
            float2 v = make_float2(accy[fc][0] * inv0, accy[fc][1] * inv0);
            *(float2*)(g_y + (size_t)(b * NPIX + row0) * C2H + col) = v;
        }
        if (row1 < NPIX) {
            float2 v = make_float2(accy[fc][2] * inv1, accy[fc][3] * inv1);
            *(float2*)(g_y + (size_t)(b * NPIX + row1) * C2H + col) = v;
        }
    }
}

// ---- out proj: o2[o,m] = sum_c y_w[o,c]*yflat[c*NPIX+m] (raw view) ----
__global__ void outproj_k(const float* __restrict__ y_w) {
    __shared__ float sW[32][132];
    __shared__ float sX[32][68];
    int t  = threadIdx.x;
    int b  = blockIdx.z;
    int o0 = blockIdx.y * 128;
    int m0 = blockIdx.x * 64;
    const float* yb = g_y + (size_t)b * NPIX * C2H;    // flat, viewed (C2, NPIX)

    int ty = t >> 4, tx = t & 15;
    int row = ty * 8, col = tx * 4;

    float acc[8][4];
    #pragma unroll
    for (int u = 0; u < 8; u++)
        #pragma unroll
        for (int v = 0; v < 4; v++) acc[u][v] = 0.f;

    for (int k0 = 0; k0 < C2H; k0 += 32) {
        #pragma unroll
        for (int it = 0; it < 4; it++) {
            int o  = (t >> 3) + it * 32;
            int k4 = (t & 7) * 4;
            float4 v = *(const float4*)(y_w + (size_t)(o0 + o) * C2H + k0 + k4);
            sW[k4+0][o] = v.x; sW[k4+1][o] = v.y;
            sW[k4+2][o] = v.z; sW[k4+3][o] = v.w;
        }
        #pragma unroll
        for (int it = 0; it < 8; it++) {
            int idx = t + it * 256;
            int kk = idx >> 6, j = idx & 63;
            sX[kk][j] = yb[(size_t)(k0 + kk) * NPIX + m0 + j];   // PAD covers tail
        }
        __syncthreads();

        #pragma unroll 4
        for (int kk = 0; kk < 32; kk++) {
            float4 a0 = *(const float4*)&sW[kk][row];
            float4 a1 = *(const float4*)&sW[kk][row + 4];
            float4 bx = *(const float4*)&sX[kk][col];
            float ra[8] = {a0.x,a0.y,a0.z,a0.w,a1.x,a1.y,a1.z,a1.w};
            float rb[4] = {bx.x,bx.y,bx.z,bx.w};
            #pragma unroll
            for (int u = 0; u < 8; u++)
                #pragma unroll
                for (int v = 0; v < 4; v++)
                    acc[u][v] = fmaf(ra[u], rb[v], acc[u][v]);
        }
        __syncthreads();
    }

    #pragma unroll
    for (int u = 0; u < 8; u++) {
        int o = o0 + row + u;
        #pragma unroll
        for (int v = 0; v < 4; v++) {
            int m = m0 + col + v;
            if (m < NPIX)
                g_o2[(size_t)(b * CCH + o) * XLD + m] = acc[u][v];
        }
    }
}

// ---------------- BN stats ----------------
__global__ void bnstats_k() {
    int c = blockIdx.x;
    int t = threadIdx.x;
    __shared__ double s1[256];
    __shared__ double s2[256];
    double a = 0.0, b2 = 0.0;
    for (int b = 0; b < BB; b++) {
        const float* p = g_o2 + (size_t)(b * CCH + c) * XLD;
        for (int m = t; m < NPIX; m += 256) {
            double v = (double)p[m];
            a  += v;
            b2 += v * v;
        }
    }
    s1[t] = a; s2[t] = b2; __syncthreads();
    for (int s = 128; s > 0; s >>= 1) {
        if (t < s) { s1[t] += s1[t + s]; s2[t] += s2[t + s]; }
        __syncthreads();
    }
    if (t == 0) {
        double cnt  = (double)(BB * NPIX);
        double mean = s1[0] / cnt;
        double var  = s2[0] / cnt - mean * mean;
        g_mean[c] = (float)mean;
        g_rstd[c] = (float)(1.0 / sqrt(var + (double)EPSV));
    }
}

// ---------------- BN apply + residual + ReLU ----------------
__global__ void epilogue_k(const float* __restrict__ bn_w,
                           const float* __restrict__ bn_b,
                           float* __restrict__ out)
{
    int idx = blockIdx.x * blockDim.x + threadIdx.x;
    if (idx >= BB*CCH*NPIX) return;
    int n  = idx % NPIX;
    int bc = idx / NPIX;
    int c  = bc % CCH;
    size_t off = (size_t)bc * XLD + n;
    float v = (g_o2[off] - g_mean[c]) * g_rstd[c] * bn_w[c] + bn_b[c] + g_xp[off];
    out[idx] = fmaxf(v, 0.f);
}

// ---------------- launch ----------------
extern "C" void kernel_launch(void* const* d_in, const int* in_sizes, int n_in,
                              void* d_out, int out_size)
{
    const float* x       = (const float*)d_in[0];
    const float* theta_w = (const float*)d_in[1];
    const float* phi_w   = (const float*)d_in[2];
    const float* g_w     = (const float*)d_in[3];
    const float* y_w     = (const float*)d_in[4];
    const float* bn_w    = (const float*)d_in[5];
    const float* bn_b    = (const float*)d_in[6];
    float* out = (float*)d_out;

    cudaFuncSetAttribute(flash_k, cudaFuncAttributeMaxDynamicSharedMemorySize,
                         SMEM_FLASH);

    { int n = BB*CCH*NPIX; pool_k<<<(n + 255) / 256, 256>>>(x); }

    { dim3 grid(63, 3, BB); proj3_k<<<grid, 256>>>(theta_w, phi_w, g_w); }

    // fused score + softmax + AV
    { dim3 grid(32, BB); flash_k<<<grid, 256, SMEM_FLASH>>>(); }

    { dim3 grid(63, 2, BB); outproj_k<<<grid, 256>>>(y_w); }

    bnstats_k<<<CCH, 256>>>();

    { int n = BB*CCH*NPIX; epilogue_k<<<(n + 255) / 256, 256>>>(bn_w, bn_b, out); }
}

// round 8
// speedup vs baseline: 4.6772x; 1.1579x over previous
#include <cuda_runtime.h>
#include <cuda_bf16.h>
#include <math.h>
#include <stdint.h>

// ---------------- problem constants ----------------
#define BB    4
#define CCH   256
#define C2H   128
#define HO    63
#define WO    63
#define NPIX  (HO*WO)      // 3969
#define XLD   3972         // padded fp32 stride for xp/o2
#define XB    3976         // padded bf16 stride (16B-aligned rows) for xp^T sources
#define YB    3976         // padded bf16 stride for y raw-view rows
#define MLD   4096         // bf16 m-stride for g (mult of 64)
#define HIN   128
#define WIN   128
#define EPSV  1e-5f
#define PAD   32768

// ---------------- scratch (device globals; zero-initialized) ----------------
__device__ __align__(256) float g_xp [BB*CCH*XLD + PAD];              // pooled (B,C,n) fp32
__device__ __align__(256) float g_o2 [BB*CCH*XLD + PAD];              // pre-BN
__device__ float g_mean[CCH];
__device__ float g_rstd[CCH];

__device__ __align__(256) __nv_bfloat16 g_xph[BB*CCH*XB + PAD];       // xp bf16 hi (C-major rows)
__device__ __align__(256) __nv_bfloat16 g_xpl[BB*CCH*XB + PAD];       // xp bf16 lo
__device__ __align__(256) __nv_bfloat16 g_thw_hi[128*256], g_thw_lo[128*256];
__device__ __align__(256) __nv_bfloat16 g_phw_hi[128*256], g_phw_lo[128*256];
__device__ __align__(256) __nv_bfloat16 g_gw_hi [128*256], g_gw_lo [128*256];
__device__ __align__(256) __nv_bfloat16 g_yw_hi [256*128], g_yw_lo [256*128];

__device__ __align__(256) __nv_bfloat16 g_th_hi[BB*NPIX*C2H + PAD];   // theta (B,N,C2)
__device__ __align__(256) __nv_bfloat16 g_th_lo[BB*NPIX*C2H + PAD];
__device__ __align__(256) __nv_bfloat16 g_ph_hi[BB*NPIX*C2H + PAD];   // phi   (B,M,C2)
__device__ __align__(256) __nv_bfloat16 g_ph_lo[BB*NPIX*C2H + PAD];
__device__ __align__(256) __nv_bfloat16 g_gc_hi[BB*C2H*MLD + PAD];    // g (B,C2,MLD) tail=0
__device__ __align__(256) __nv_bfloat16 g_gc_lo[BB*C2H*MLD + PAD];
__device__ __align__(256) __nv_bfloat16 g_yv_hi[BB*C2H*YB + PAD];     // y raw-view (B,C2,m)
__device__ __align__(256) __nv_bfloat16 g_yv_lo[BB*C2H*YB + PAD];

// ---------------- common asm helpers ----------------
#define MMA16816(d, a, b)                                                   \
    asm volatile("mma.sync.aligned.m16n8k16.row.col.f32.bf16.bf16.f32 "     \
                 "{%0,%1,%2,%3},{%4,%5,%6,%7},{%8,%9},{%0,%1,%2,%3};"       \
                 : "+f"((d)[0]), "+f"((d)[1]), "+f"((d)[2]), "+f"((d)[3])   \
                 : "r"((a)[0]), "r"((a)[1]), "r"((a)[2]), "r"((a)[3]),      \
                   "r"((b)[0]), "r"((b)[1]))

#define LDSM4(r, p)                                                         \
    asm volatile("ldmatrix.sync.aligned.m8n8.x4.shared.b16 "                \
                 "{%0,%1,%2,%3}, [%4];"                                     \
                 : "=r"((r)[0]), "=r"((r)[1]), "=r"((r)[2]), "=r"((r)[3])   \
                 : "r"(p))

#define LDSM4T(r, p)                                                        \
    asm volatile("ldmatrix.sync.aligned.m8n8.x4.trans.shared.b16 "          \
                 "{%0,%1,%2,%3}, [%4];"                                     \
                 : "=r"((r)[0]), "=r"((r)[1]), "=r"((r)[2]), "=r"((r)[3])   \
                 : "r"(p))

#define CPA16(dst, src)                                                     \
    asm volatile("cp.async.cg.shared.global [%0], [%1], 16;"                \
                 :: "r"(dst), "l"(src) : "memory")

__device__ __forceinline__ uint32_t pk_bf2(float x, float y) {
    __nv_bfloat162 h = __floats2bfloat162_rn(x, y);
    return *(uint32_t*)&h;
}

// ---------------- 3x3/2 VALID max pool (+ bf16 split emit) ----------------
__global__ void pool_k(const float* __restrict__ x) {
    int idx = blockIdx.x * blockDim.x + threadIdx.x;
    if (idx >= BB*CCH*NPIX) return;
    int n  = idx % NPIX;
    int bc = idx / NPIX;
    int ow = n % WO, oh = n / WO;
    const float* p = x + (size_t)bc * (HIN*WIN) + (oh*2) * WIN + (ow*2);
    float m = -INFINITY;
    #pragma unroll
    for (int i = 0; i < 3; i++) {
        m = fmaxf(m, p[i*WIN + 0]);
        m = fmaxf(m, p[i*WIN + 1]);
        m = fmaxf(m, p[i*WIN + 2]);
    }
    g_xp[(size_t)bc * XLD + n] = m;
    __nv_bfloat16 hi = __float2bfloat16(m);
    g_xph[(size_t)bc * XB + n] = hi;
    g_xpl[(size_t)bc * XB + n] = __float2bfloat16(m - __bfloat162float(hi));
}

// ---------------- weight split prep ----------------
__global__ void wsplit_k(const float* __restrict__ thW, const float* __restrict__ phW,
                         const float* __restrict__ gW,  const float* __restrict__ yW) {
    int idx = blockIdx.x * blockDim.x + threadIdx.x;
    if (idx >= 4*32768) return;
    int arr = idx >> 15, off = idx & 32767;
    const float* s = (arr == 0) ? thW : (arr == 1) ? phW : (arr == 2) ? gW : yW;
    float v = s[off];
    __nv_bfloat16 hi = __float2bfloat16(v);
    __nv_bfloat16 lo = __float2bfloat16(v - __bfloat162float(hi));
    if      (arr == 0) { g_thw_hi[off] = hi; g_thw_lo[off] = lo; }
    else if (arr == 1) { g_phw_hi[off] = hi; g_phw_lo[off] = lo; }
    else if (arr == 2) { g_gw_hi [off] = hi; g_gw_lo [off] = lo; }
    else               { g_yw_hi [off] = hi; g_yw_lo [off] = lo; }
}

// ================ split-bf16 TN MMA for projections / outproj ================
// C[i, j] = sum_k A[i,k] (K-fast) * X[k,j] (K-slow rows), B-frags via ldmatrix.trans.
#define PJ_SW  144               // sW row bytes (64 bf16 + pad)
#define PJ_SX  272               // sX row bytes (128 bf16 + pad)
#define PJ_WB  (128*PJ_SW)       // 18432
#define PJ_XTB (64*PJ_SX)        // 17408
#define PJ_STG (PJ_WB + PJ_XTB)  // 35840
#define PJ_SMEM (2*PJ_STG)       // 71680

// ---- projections: grid (32 j-tiles, 3 w, BB). I=128, K=256 (4 chunks). ----
__global__ __launch_bounds__(256) void projmma_k() {
    extern __shared__ __align__(256) char smem[];
    uint32_t sb = (uint32_t)__cvta_generic_to_shared(smem);
    int t = threadIdx.x, lane = t & 31, wid = t >> 5;
    int b = blockIdx.z, w = blockIdx.y;
    int j0 = blockIdx.x * 128;

    const __nv_bfloat16* Whi = (w == 0) ? g_thw_hi : (w == 1) ? g_phw_hi : g_gw_hi;
    const __nv_bfloat16* Wlo = (w == 0) ? g_thw_lo : (w == 1) ? g_phw_lo : g_gw_lo;
    const __nv_bfloat16* Xhi = g_xph + (size_t)b * CCH * XB;
    const __nv_bfloat16* Xlo = g_xpl + (size_t)b * CCH * XB;

    int gq = lane >> 2, tg = lane & 3;
    int a_ro = (lane & 7) + ((lane >> 3) & 1) * 8;
    int a_co = (lane >> 4) * 8;
    int trow = (lane & 7) + ((lane >> 3) & 1) * 8;   // k row within 16
    int tcol = (lane >> 4) * 8;                      // n col offset 0/8

    float acc[16][4];
    #pragma unroll
    for (int fj = 0; fj < 16; fj++)
        #pragma unroll
        for (int e = 0; e < 4; e++) acc[fj][e] = 0.f;

    const int KC = 4, TOT = 12;
    auto issue = [&](int s) {
        int ph = s / KC, k0 = (s - ph * KC) * 64;
        const __nv_bfloat16* Wp = (ph == 2) ? Wlo : Whi;
        const __nv_bfloat16* Xp = (ph == 1) ? Xlo : Xhi;
        uint32_t stg = sb + (s & 1) * PJ_STG;
        #pragma unroll
        for (int it = 0; it < 4; it++) {            // W: 128 rows x 64k
            int cid = t + it * 256;
            int r = cid >> 3, q = cid & 7;
            CPA16(stg + r * PJ_SW + q * 16, Wp + r * 256 + k0 + q * 8);
        }
        #pragma unroll
        for (int it = 0; it < 4; it++) {            // X: 64 k-rows x 128n
            int cid = t + it * 256;
            int r = cid >> 4, q = cid & 15;
            CPA16(stg + PJ_WB + r * PJ_SX + q * 16,
                  Xp + (size_t)(k0 + r) * XB + j0 + q * 8);
        }
        asm volatile("cp.async.commit_group;" ::: "memory");
    };
    issue(0);

    for (int s = 0; s < TOT; s++) {
        if (s + 1 < TOT) {
            issue(s + 1);
            asm volatile("cp.async.wait_group 1;" ::: "memory");
        } else {
            asm volatile("cp.async.wait_group 0;" ::: "memory");
        }
        __syncthreads();
        uint32_t stg = sb + (s & 1) * PJ_STG;
        uint32_t aB = stg + (wid * 16 + a_ro) * PJ_SW + a_co * 2;
        uint32_t xB = stg + PJ_WB + trow * PJ_SX + tcol * 2;
        #pragma unroll
        for (int k16 = 0; k16 < 4; k16++) {
            uint32_t a[4];
            LDSM4(a, aB + k16 * 32);
            #pragma unroll
            for (int jb = 0; jb < 8; jb++) {
                uint32_t r[4];
                LDSM4T(r, xB + k16 * 16 * PJ_SX + jb * 32);
                MMA16816(acc[2*jb],     a, r);
                MMA16816(acc[2*jb + 1], a, r + 2);
            }
        }
        __syncthreads();
    }

    if (w < 2) {
        // stage fp32, then transposed coalesced bf16 hi/lo writeout
        float* stage = (float*)smem;                 // [128][132]
        int r0 = wid * 16 + gq, r1 = r0 + 8;
        #pragma unroll
        for (int fj = 0; fj < 16; fj++) {
            int c = fj * 8 + tg * 2;
            *(float2*)&stage[r0 * 132 + c] = make_float2(acc[fj][0], acc[fj][1]);
            *(float2*)&stage[r1 * 132 + c] = make_float2(acc[fj][2], acc[fj][3]);
        }
        __syncthreads();
        int j = t >> 1, half = t & 1;
        int n = j0 + j;
        if (n < NPIX) {
            size_t base = (size_t)(b * NPIX + n) * C2H + half * 64;
            __nv_bfloat16* TH = ((w == 0) ? g_th_hi : g_ph_hi) + base;
            __nv_bfloat16* TL = ((w == 0) ? g_th_lo : g_ph_lo) + base;
            uint32_t hb[32], lb[32];
            #pragma unroll
            for (int i = 0; i < 64; i += 2) {
                float v0 = stage[(half * 64 + i)     * 132 + j];
                float v1 = stage[(half * 64 + i + 1) * 132 + j];
                float h0 = __bfloat162float(__float2bfloat16(v0));
                float h1 = __bfloat162float(__float2bfloat16(v1));
                hb[i >> 1] = pk_bf2(h0, h1);
                lb[i >> 1] = pk_bf2(v0 - h0, v1 - h1);
            }
            #pragma unroll
            for (int u = 0; u < 8; u++) {
                ((uint4*)TH)[u] = ((uint4*)hb)[u];
                ((uint4*)TL)[u] = ((uint4*)lb)[u];
            }
        }
    } else {
        // g: direct (C2, MLD) store
        int i0r = wid * 16 + gq;
        #pragma unroll
        for (int fj = 0; fj < 16; fj++) {
            int jj = j0 + fj * 8 + tg * 2;
            #pragma unroll
            for (int h = 0; h < 2; h++) {
                int i = i0r + h * 8;
                float v0 = acc[fj][2*h], v1 = acc[fj][2*h + 1];
                size_t base = (size_t)(b * C2H + i) * MLD + jj;
                float h0 = __bfloat162float(__float2bfloat16(v0));
                float h1 = __bfloat162float(__float2bfloat16(v1));
                if (jj + 1 < NPIX) {
                    *(uint32_t*)(g_gc_hi + base) = pk_bf2(h0, h1);
                    *(uint32_t*)(g_gc_lo + base) = pk_bf2(v0 - h0, v1 - h1);
                } else if (jj < NPIX) {
                    g_gc_hi[base] = __float2bfloat16(v0);
                    g_gc_lo[base] = __float2bfloat16(v0 - h0);
                }
            }
        }
    }
}

// ---- outproj: grid (32 j-tiles, 2 o-tiles, BB). I=128/tile, K=128 (2 chunks). ----
__global__ __launch_bounds__(256) void opmma_k() {
    extern __shared__ __align__(256) char smem[];
    uint32_t sb = (uint32_t)__cvta_generic_to_shared(smem);
    int t = threadIdx.x, lane = t & 31, wid = t >> 5;
    int b = blockIdx.z;
    int o0 = blockIdx.y * 128;
    int j0 = blockIdx.x * 128;

    const __nv_bfloat16* Xhi = g_yv_hi + (size_t)b * C2H * YB;
    const __nv_bfloat16* Xlo = g_yv_lo + (size_t)b * C2H * YB;

    int gq = lane >> 2, tg = lane & 3;
    int a_ro = (lane & 7) + ((lane >> 3) & 1) * 8;
    int a_co = (lane >> 4) * 8;
    int trow = (lane & 7) + ((lane >> 3) & 1) * 8;
    int tcol = (lane >> 4) * 8;

    float acc[16][4];
    #pragma unroll
    for (int fj = 0; fj < 16; fj++)
        #pragma unroll
        for (int e = 0; e < 4; e++) acc[fj][e] = 0.f;

    const int KC = 2, TOT = 6;
    auto issue = [&](int s) {
        int ph = s / KC, k0 = (s - ph * KC) * 64;
        const __nv_bfloat16* Wp = (ph == 2) ? g_yw_lo : g_yw_hi;
        const __nv_bfloat16* Xp = (ph == 1) ? Xlo : Xhi;
        uint32_t stg = sb + (s & 1) * PJ_STG;
        #pragma unroll
        for (int it = 0; it < 4; it++) {
            int cid = t + it * 256;
            int r = cid >> 3, q = cid & 7;
            CPA16(stg + r * PJ_SW + q * 16, Wp + (o0 + r) * 128 + k0 + q * 8);
        }
        #pragma unroll
        for (int it = 0; it < 4; it++) {
            int cid = t + it * 256;
            int r = cid >> 4, q = cid & 15;
            CPA16(stg + PJ_WB + r * PJ_SX + q * 16,
                  Xp + (size_t)(k0 + r) * YB + j0 + q * 8);
        }
        asm volatile("cp.async.commit_group;" ::: "memory");
    };
    issue(0);

    for (int s = 0; s < TOT; s++) {
        if (s + 1 < TOT) {
            issue(s + 1);
            asm volatile("cp.async.wait_group 1;" ::: "memory");
        } else {
            asm volatile("cp.async.wait_group 0;" ::: "memory");
        }
        __syncthreads();
        uint32_t stg = sb + (s & 1) * PJ_STG;
        uint32_t aB = stg + (wid * 16 + a_ro) * PJ_SW + a_co * 2;
        uint32_t xB = stg + PJ_WB + trow * PJ_SX + tcol * 2;
        #pragma unroll
        for (int k16 = 0; k16 < 4; k16++) {
            uint32_t a[4];
            LDSM4(a, aB + k16 * 32);
            #pragma unroll
            for (int jb = 0; jb < 8; jb++) {
                uint32_t r[4];
                LDSM4T(r, xB + k16 * 16 * PJ_SX + jb * 32);
                MMA16816(acc[2*jb],     a, r);
                MMA16816(acc[2*jb + 1], a, r + 2);
            }
        }
        __syncthreads();
    }

    int i0r = o0 + wid * 16 + gq;
    #pragma unroll
    for (int fj = 0; fj < 16; fj++) {
        int jj = j0 + fj * 8 + tg * 2;
        #pragma unroll
        for (int h = 0; h < 2; h++) {
            int i = i0r + h * 8;
            size_t base = (size_t)(b * CCH + i) * XLD + jj;
            if (jj + 1 < NPIX)
                *(float2*)(g_o2 + base) = make_float2(acc[fj][2*h], acc[fj][2*h + 1]);
            else if (jj < NPIX)
                g_o2[base] = acc[fj][2*h];
        }
    }
}

// ================= fused flash attention (split-bf16 mma.sync) =================
#define TM   64
#define NT   63
#define THRB 272
#define GRB  144
#define SM_TH_HI 0
#define SM_TH_LO 34816
#define SM_STG   69632
#define ST_PH_HI 0
#define ST_PH_LO 17408
#define ST_G_HI  34816
#define ST_G_LO  53248
#define STG_SZ   71680
#define SMEM_FLASH (SM_STG + 2*STG_SZ)   // 212992

__global__ __launch_bounds__(256, 1) void flash_k() {
    extern __shared__ __align__(256) char smem[];
    uint32_t sb = (uint32_t)__cvta_generic_to_shared(smem);
    int t = threadIdx.x, lane = t & 31, wid = t >> 5;
    int b = blockIdx.y;
    int q0 = blockIdx.x * 128;

    #pragma unroll
    for (int it = 0; it < 8; it++) {
        int cid = t + it * 256;
        int r = cid >> 4, q = cid & 15;
        size_t off = (size_t)(b * NPIX + q0 + r) * C2H + q * 8;
        CPA16(sb + SM_TH_HI + r * THRB + q * 16, g_th_hi + off);
        CPA16(sb + SM_TH_LO + r * THRB + q * 16, g_th_lo + off);
    }
    asm volatile("cp.async.commit_group;" ::: "memory");

    auto issue_stage = [&](int s) {
        int m0 = s * TM;
        uint32_t stg = sb + SM_STG + (s & 1) * STG_SZ;
        #pragma unroll
        for (int it = 0; it < 4; it++) {
            int cid = t + it * 256;
            int r = cid >> 4, q = cid & 15;
            size_t off = (size_t)(b * NPIX + m0 + r) * C2H + q * 8;
            CPA16(stg + ST_PH_HI + r * THRB + q * 16, g_ph_hi + off);
            CPA16(stg + ST_PH_LO + r * THRB + q * 16, g_ph_lo + off);
        }
        #pragma unroll
        for (int it = 0; it < 4; it++) {
            int cid = t + it * 256;
            int r = cid >> 3, q = cid & 7;
            size_t off = (size_t)(b * C2H + r) * MLD + m0 + q * 8;
            CPA16(stg + ST_G_HI + r * GRB + q * 16, g_gc_hi + off);
            CPA16(stg + ST_G_LO + r * GRB + q * 16, g_gc_lo + off);
        }
        asm volatile("cp.async.commit_group;" ::: "memory");
    };
    issue_stage(0);

    int gq = lane >> 2, tg = lane & 3;
    int a_ro = (lane & 7) + ((lane >> 3) & 1) * 8;
    int a_co = (lane >> 4) * 8;
    int b_ro = (lane & 7) + ((lane >> 4) & 1) * 8;
    int b_co = ((lane >> 3) & 1) * 8;

    uint32_t thA_hi = sb + SM_TH_HI + (wid * 16 + a_ro) * THRB + a_co * 2;
    uint32_t thA_lo = sb + SM_TH_LO + (wid * 16 + a_ro) * THRB + a_co * 2;

    float m0r = -INFINITY, m1r = -INFINITY;
    float l0r = 0.f, l1r = 0.f;
    float accy[16][4];
    #pragma unroll
    for (int fc = 0; fc < 16; fc++)
        #pragma unroll
        for (int e = 0; e < 4; e++) accy[fc][e] = 0.f;

    for (int itr = 0; itr < NT; itr++) {
        if (itr + 1 < NT) {
            issue_stage(itr + 1);
            asm volatile("cp.async.wait_group 1;" ::: "memory");
        } else {
            asm volatile("cp.async.wait_group 0;" ::: "memory");
        }
        __syncthreads();
        uint32_t stg = sb + SM_STG + (itr & 1) * STG_SZ;

        float s[8][4];
        #pragma unroll
        for (int fj = 0; fj < 8; fj++)
            #pragma unroll
            for (int e = 0; e < 4; e++) s[fj][e] = 0.f;

        #pragma unroll
        for (int ph = 0; ph < 3; ph++) {
            uint32_t ab = (ph == 2) ? thA_lo : thA_hi;
            uint32_t bb = stg + ((ph == 1) ? ST_PH_LO : ST_PH_HI)
                        + b_ro * THRB + b_co * 2;
            #pragma unroll
            for (int k16 = 0; k16 < 8; k16++) {
                uint32_t a[4];
                LDSM4(a, ab + k16 * 32);
                #pragma unroll
                for (int mb = 0; mb < 4; mb++) {
                    uint32_t r[4];
                    LDSM4(r, bb + mb * 16 * THRB + k16 * 32);
                    MMA16816(s[2*mb],     a, r);
                    MMA16816(s[2*mb + 1], a, r + 2);
                }
            }
        }

        if (itr == NT - 1) {
            int mbase = itr * TM;
            #pragma unroll
            for (int fj = 0; fj < 8; fj++) {
                int c = mbase + fj * 8 + tg * 2;
                if (c     >= NPIX) { s[fj][0] = -INFINITY; s[fj][2] = -INFINITY; }
                if (c + 1 >= NPIX) { s[fj][1] = -INFINITY; s[fj][3] = -INFINITY; }
            }
        }

        float mx0 = -INFINITY, mx1 = -INFINITY;
        #pragma unroll
        for (int fj = 0; fj < 8; fj++) {
            mx0 = fmaxf(mx0, fmaxf(s[fj][0], s[fj][1]));
            mx1 = fmaxf(mx1, fmaxf(s[fj][2], s[fj][3]));
        }
        mx0 = fmaxf(mx0, __shfl_xor_sync(~0u, mx0, 1));
        mx0 = fmaxf(mx0, __shfl_xor_sync(~0u, mx0, 2));
        mx1 = fmaxf(mx1, __shfl_xor_sync(~0u, mx1, 1));
        mx1 = fmaxf(mx1, __shfl_xor_sync(~0u, mx1, 2));

        float mn0 = fmaxf(m0r, mx0), mn1 = fmaxf(m1r, mx1);
        float sc0 = expf(m0r - mn0), sc1 = expf(m1r - mn1);
        m0r = mn0; m1r = mn1;

        uint32_t phh0[8], phh1[8], phl0[8], phl1[8];
        float sum0 = 0.f, sum1 = 0.f;
        #pragma unroll
        for (int fj = 0; fj < 8; fj++) {
            float p0 = expf(s[fj][0] - mn0);
            float p1 = expf(s[fj][1] - mn0);
            float p2 = expf(s[fj][2] - mn1);
            float p3 = expf(s[fj][3] - mn1);
            sum0 += p0 + p1; sum1 += p2 + p3;
            float h0 = __bfloat162float(__float2bfloat16(p0));
            float h1 = __bfloat162float(__float2bfloat16(p1));
            float h2 = __bfloat162float(__float2bfloat16(p2));
            float h3 = __bfloat162float(__float2bfloat16(p3));
            phh0[fj] = pk_bf2(h0, h1);
            phh1[fj] = pk_bf2(h2, h3);
            phl0[fj] = pk_bf2(p0 - h0, p1 - h1);
            phl1[fj] = pk_bf2(p2 - h2, p3 - h3);
        }
        sum0 += __shfl_xor_sync(~0u, sum0, 1);
        sum0 += __shfl_xor_sync(~0u, sum0, 2);
        sum1 += __shfl_xor_sync(~0u, sum1, 1);
        sum1 += __shfl_xor_sync(~0u, sum1, 2);
        l0r = l0r * sc0 + sum0;
        l1r = l1r * sc1 + sum1;

        #pragma unroll
        for (int fc = 0; fc < 16; fc++) {
            accy[fc][0] *= sc0; accy[fc][1] *= sc0;
            accy[fc][2] *= sc1; accy[fc][3] *= sc1;
        }

        #pragma unroll
        for (int ph = 0; ph < 3; ph++) {
            uint32_t gb = stg + ((ph == 1) ? ST_G_LO : ST_G_HI)
                        + b_ro * GRB + b_co * 2;
            uint32_t* pa0 = (ph == 2) ? phl0 : phh0;
            uint32_t* pa1 = (ph == 2) ? phl1 : phh1;
            #pragma unroll
            for (int kw = 0; kw < 4; kw++) {
                uint32_t a[4] = { pa0[2*kw], pa1[2*kw], pa0[2*kw+1], pa1[2*kw+1] };
                #pragma unroll
                for (int fc16 = 0; fc16 < 8; fc16++) {
                    uint32_t r[4];
                    LDSM4(r, gb + fc16 * 16 * GRB + kw * 32);
                    MMA16816(accy[2*fc16],     a, r);
                    MMA16816(accy[2*fc16 + 1], a, r + 2);
                }
            }
        }
        __syncthreads();
    }

    // finalize: y /= l, emit directly in raw-view (c, m) bf16 hi/lo layout
    float inv0 = 1.f / l0r, inv1 = 1.f / l1r;
    int row0 = q0 + wid * 16 + gq;
    int row1 = row0 + 8;
    auto emit = [&](int n, int cc, float v) {
        if (n >= NPIX) return;
        uint32_t q = (uint32_t)n * 128u + (uint32_t)cc;
        uint32_t c = q / 3969u;
        uint32_t m = q - c * 3969u;
        size_t a = (size_t)(b * C2H + c) * YB + m;
        __nv_bfloat16 hi = __float2bfloat16(v);
        g_yv_hi[a] = hi;
        g_yv_lo[a] = __float2bfloat16(v - __bfloat162float(hi));
    };
    #pragma unroll
    for (int fc = 0; fc < 16; fc++) {
        int col = fc * 8 + tg * 2;
        emit(row0, col,     accy[fc][0] * inv0);
        emit(row0, col + 1, accy[fc][1] * inv0);
        emit(row1, col,     accy[fc][2] * inv1);
        emit(row1, col + 1, accy[fc][3] * inv1);
    }
}

// ---------------- BN stats ----------------
__global__ void bnstats_k() {
    int c = blockIdx.x;
    int t = threadIdx.x;
    __shared__ double s1[256];
    __shared__ double s2[256];
    double a = 0.0, b2 = 0.0;
    for (int b = 0; b < BB; b++) {
        const float* p = g_o2 + (size_t)(b * CCH + c) * XLD;
        for (int m = t; m < NPIX; m += 256) {
            double v = (double)p[m];
            a  += v;
            b2 += v * v;
        }
    }
    s1[t] = a; s2[t] = b2; __syncthreads();
    for (int s = 128; s > 0; s >>= 1) {
        if (t < s) { s1[t] += s1[t + s]; s2[t] += s2[t + s]; }
        __syncthreads();
    }
    if (t == 0) {
        double cnt  = (double)(BB * NPIX);
        double mean = s1[0] / cnt;
        double var  = s2[0] / cnt - mean * mean;
        g_mean[c] = (float)mean;
        g_rstd[c] = (float)(1.0 / sqrt(var + (double)EPSV));
    }
}

// ---------------- BN apply + residual + ReLU ----------------
__global__ void epilogue_k(const float* __restrict__ bn_w,
                           const float* __restrict__ bn_b,
                           float* __restrict__ out)
{
    int idx = blockIdx.x * blockDim.x + threadIdx.x;
    if (idx >= BB*CCH*NPIX) return;
    int n  = idx % NPIX;
    int bc = idx / NPIX;
    int c  = bc % CCH;
    size_t off = (size_t)bc * XLD + n;
    float v = (g_o2[off] - g_mean[c]) * g_rstd[c] * bn_w[c] + bn_b[c] + g_xp[off];
    out[idx] = fmaxf(v, 0.f);
}

// ---------------- launch ----------------
extern "C" void kernel_launch(void* const* d_in, const int* in_sizes, int n_in,
                              void* d_out, int out_size)
{
    const float* x       = (const float*)d_in[0];
    const float* theta_w = (const float*)d_in[1];
    const float* phi_w   = (const float*)d_in[2];
    const float* g_w     = (const float*)d_in[3];
    const float* y_w     = (const float*)d_in[4];
    const float* bn_w    = (const float*)d_in[5];
    const float* bn_b    = (const float*)d_in[6];
    float* out = (float*)d_out;

    cudaFuncSetAttribute(flash_k, cudaFuncAttributeMaxDynamicSharedMemorySize,
                         SMEM_FLASH);
    cudaFuncSetAttribute(projmma_k, cudaFuncAttributeMaxDynamicSharedMemorySize,
                         PJ_SMEM);
    cudaFuncSetAttribute(opmma_k, cudaFuncAttributeMaxDynamicSharedMemorySize,
                         PJ_SMEM);

    { int n = BB*CCH*NPIX; pool_k<<<(n + 255) / 256, 256>>>(x); }

    wsplit_k<<<512, 256>>>(theta_w, phi_w, g_w, y_w);

    { dim3 grid(32, 3, BB); projmma_k<<<grid, 256, PJ_SMEM>>>(); }

    { dim3 grid(32, BB); flash_k<<<grid, 256, SMEM_FLASH>>>(); }

    { dim3 grid(32, 2, BB); opmma_k<<<grid, 256, PJ_SMEM>>>(); }

    bnstats_k<<<CCH, 256>>>();

    { int n = BB*CCH*NPIX; epilogue_k<<<(n + 255) / 256, 256>>>(bn_w, bn_b, out); }
}